// round 2
// baseline (speedup 1.0000x reference)
#include <cuda_runtime.h>

// Problem constants
#define DIN   1024
#define DOUT  1024
#define NH    16
#define DH    64
#define BATCH 2
#define SEQ   2048
#define MTOT  (BATCH * SEQ)   // 4096 rows

// Scratch (allocation-free: __device__ globals)
// g_qkv layout: [3][B*H][T][DH]
__device__ float g_qkv[3ull * BATCH * NH * SEQ * DH];
// g_ctx layout: [B][T][H*DH] (row-major [4096, 1024])
__device__ float g_ctx[(size_t)BATCH * SEQ * DOUT];

// ---------------------------------------------------------------------------
// Kernel 1: QKV projections.  C = X @ W{q,k,v}, selected by blockIdx.z.
// 64x64 output tile, BK=16, 256 threads, 4x4 micro-tile per thread.
// Output written to g_qkv in [w][b*H+h][t][dh] layout (nBase==head*64 since
// the 64-wide N tile aligns exactly with one head).
// ---------------------------------------------------------------------------
__global__ __launch_bounds__(256) void qkv_gemm_kernel(
    const float* __restrict__ x,
    const float* __restrict__ Wq,
    const float* __restrict__ Wk,
    const float* __restrict__ Wv)
{
    const float* W = (blockIdx.z == 0) ? Wq : (blockIdx.z == 1) ? Wk : Wv;

    __shared__ float As[16][64];   // As[k][m]
    __shared__ float Bs[16][64];   // Bs[k][n]

    const int t  = threadIdx.x;
    const int tx = t & 15;         // 0..15 -> 4 output cols each
    const int ty = t >> 4;         // 0..15 -> 4 output rows each
    const int mBase = blockIdx.x * 64;
    const int nBase = blockIdx.y * 64;

    // Load indices: A tile is 64 rows x 16 cols (one float4 per thread)
    const int aRow = t >> 2;            // 0..63
    const int aC   = (t & 3) * 4;       // 0,4,8,12
    // B tile is 16 rows x 64 cols (one float4 per thread)
    const int bRow = t >> 4;            // 0..15
    const int bC   = (t & 15) * 4;      // 0..60

    float acc[4][4];
    #pragma unroll
    for (int i = 0; i < 4; i++)
        #pragma unroll
        for (int j = 0; j < 4; j++) acc[i][j] = 0.0f;

    for (int kt = 0; kt < DIN; kt += 16) {
        float4 av = *(const float4*)&x[(size_t)(mBase + aRow) * DIN + kt + aC];
        float4 bv = *(const float4*)&W[(size_t)(kt + bRow) * DOUT + nBase + bC];
        As[aC + 0][aRow] = av.x;
        As[aC + 1][aRow] = av.y;
        As[aC + 2][aRow] = av.z;
        As[aC + 3][aRow] = av.w;
        *(float4*)&Bs[bRow][bC] = bv;
        __syncthreads();

        #pragma unroll
        for (int k = 0; k < 16; k++) {
            float4 a = *(const float4*)&As[k][ty * 4];
            float4 b = *(const float4*)&Bs[k][tx * 4];
            acc[0][0] += a.x * b.x; acc[0][1] += a.x * b.y; acc[0][2] += a.x * b.z; acc[0][3] += a.x * b.w;
            acc[1][0] += a.y * b.x; acc[1][1] += a.y * b.y; acc[1][2] += a.y * b.z; acc[1][3] += a.y * b.w;
            acc[2][0] += a.z * b.x; acc[2][1] += a.z * b.y; acc[2][2] += a.z * b.z; acc[2][3] += a.z * b.w;
            acc[3][0] += a.w * b.x; acc[3][1] += a.w * b.y; acc[3][2] += a.w * b.z; acc[3][3] += a.w * b.w;
        }
        __syncthreads();
    }

    // Write to g_qkv[w][b*H + h][tpos][dh]; h == blockIdx.y, dh = tx*4..+3
    const int h = blockIdx.y;
    #pragma unroll
    for (int i = 0; i < 4; i++) {
        int m  = mBase + ty * 4 + i;
        int b  = m >> 11;            // / SEQ
        int tp = m & (SEQ - 1);      // % SEQ
        size_t dst = ((((size_t)blockIdx.z * BATCH + b) * NH + h) * SEQ + tp) * DH + tx * 4;
        float4 v = make_float4(acc[i][0], acc[i][1], acc[i][2], acc[i][3]);
        *(float4*)&g_qkv[dst] = v;
    }
}

// ---------------------------------------------------------------------------
// Kernel 2: causal flash attention, fp32.
// grid = (SEQ/128, B*H), block = 128 threads.
// Each thread owns one query row: q[64] in regs, acc[64] in regs,
// online softmax over 32-key tiles staged in shared memory.
// Writes ctx in [b][t][h*DH+d] layout for the O-projection GEMM.
// ---------------------------------------------------------------------------
__global__ __launch_bounds__(128) void attn_kernel()
{
    const size_t plane = (size_t)BATCH * NH * SEQ * DH;
    const float* Q = g_qkv;
    const float* K = g_qkv + plane;
    const float* V = g_qkv + 2 * plane;

    const int bh = blockIdx.y;
    const int qi = blockIdx.x * 128 + threadIdx.x;   // global query index (< SEQ)

    const float* Kbh = K + (size_t)bh * SEQ * DH;
    const float* Vbh = V + (size_t)bh * SEQ * DH;

    // Load this thread's query row, pre-scaled by 1/sqrt(dh)
    float q[DH];
    {
        const float* qptr = Q + ((size_t)bh * SEQ + qi) * DH;
        #pragma unroll
        for (int d = 0; d < DH; d++) q[d] = qptr[d] * 0.125f;
    }

    __shared__ float Ks[32][DH];
    __shared__ float Vs[32][DH];

    float accum[DH];
    #pragma unroll
    for (int d = 0; d < DH; d++) accum[d] = 0.0f;
    float m_run = -1e30f;
    float l_run = 0.0f;

    const int nkt = blockIdx.x * 4 + 4;   // causal: key tiles 0..nkt-1 (32 keys each)

    for (int kt = 0; kt < nkt; kt++) {
        __syncthreads();
        // Cooperative load of 32x64 K and V tiles (512 float4 each, 4/thread)
        {
            const float4* ksrc = (const float4*)(Kbh + (size_t)kt * 32 * DH);
            const float4* vsrc = (const float4*)(Vbh + (size_t)kt * 32 * DH);
            float4* kdst = (float4*)&Ks[0][0];
            float4* vdst = (float4*)&Vs[0][0];
            #pragma unroll
            for (int i = 0; i < 4; i++) {
                int idx = threadIdx.x + i * 128;
                kdst[idx] = ksrc[idx];
                vdst[idx] = vsrc[idx];
            }
        }
        __syncthreads();

        // Scores: s[j] = q . K[j]
        float s[32];
        #pragma unroll
        for (int j = 0; j < 32; j++) {
            const float4* krow = (const float4*)&Ks[j][0];
            float sum = 0.0f;
            #pragma unroll
            for (int d4 = 0; d4 < 16; d4++) {
                float4 kv = krow[d4];
                sum += q[d4 * 4 + 0] * kv.x;
                sum += q[d4 * 4 + 1] * kv.y;
                sum += q[d4 * 4 + 2] * kv.z;
                sum += q[d4 * 4 + 3] * kv.w;
            }
            s[j] = sum;
        }

        // Causal mask (only the last few tiles of the block need it)
        const int k0 = kt * 32;
        if (k0 + 31 > qi) {
            #pragma unroll
            for (int j = 0; j < 32; j++)
                if (k0 + j > qi) s[j] = -1e30f;
        }

        float tmax = -1e30f;
        #pragma unroll
        for (int j = 0; j < 32; j++) tmax = fmaxf(tmax, s[j]);

        if (tmax > -1e29f) {   // tile has at least one unmasked key for this row
            float m_new = fmaxf(m_run, tmax);
            float corr  = __expf(m_run - m_new);
            float psum  = 0.0f;
            #pragma unroll
            for (int j = 0; j < 32; j++) {
                s[j] = __expf(s[j] - m_new);
                psum += s[j];
            }
            l_run = l_run * corr + psum;
            #pragma unroll
            for (int d = 0; d < DH; d++) accum[d] *= corr;
            #pragma unroll
            for (int j = 0; j < 32; j++) {
                const float p = s[j];
                const float4* vrow = (const float4*)&Vs[j][0];
                #pragma unroll
                for (int d4 = 0; d4 < 16; d4++) {
                    float4 vv = vrow[d4];
                    accum[d4 * 4 + 0] += p * vv.x;
                    accum[d4 * 4 + 1] += p * vv.y;
                    accum[d4 * 4 + 2] += p * vv.z;
                    accum[d4 * 4 + 3] += p * vv.w;
                }
            }
            m_run = m_new;
        }
    }

    // Normalize + write ctx[b][t][h*DH + d]
    const float inv = 1.0f / l_run;
    const int b = bh >> 4;       // / NH
    const int h = bh & (NH - 1); // % NH
    float* out = g_ctx + ((size_t)(b * SEQ + qi)) * DOUT + h * DH;
    #pragma unroll
    for (int d4 = 0; d4 < 16; d4++) {
        float4 v = make_float4(accum[d4 * 4 + 0] * inv, accum[d4 * 4 + 1] * inv,
                               accum[d4 * 4 + 2] * inv, accum[d4 * 4 + 3] * inv);
        *(float4*)&out[d4 * 4] = v;
    }
}

// ---------------------------------------------------------------------------
// Kernel 3: output projection.  out = ctx @ Wo + bo
// Same tiling as kernel 1; row-major [4096, 1024] output.
// ---------------------------------------------------------------------------
__global__ __launch_bounds__(256) void oproj_gemm_kernel(
    const float* __restrict__ Wo,
    const float* __restrict__ bo,
    float* __restrict__ out)
{
    __shared__ float As[16][64];
    __shared__ float Bs[16][64];

    const int t  = threadIdx.x;
    const int tx = t & 15;
    const int ty = t >> 4;
    const int mBase = blockIdx.x * 64;
    const int nBase = blockIdx.y * 64;

    const int aRow = t >> 2;
    const int aC   = (t & 3) * 4;
    const int bRow = t >> 4;
    const int bC   = (t & 15) * 4;

    float acc[4][4];
    #pragma unroll
    for (int i = 0; i < 4; i++)
        #pragma unroll
        for (int j = 0; j < 4; j++) acc[i][j] = 0.0f;

    for (int kt = 0; kt < DOUT; kt += 16) {
        float4 av = *(const float4*)&g_ctx[(size_t)(mBase + aRow) * DOUT + kt + aC];
        float4 bv = *(const float4*)&Wo[(size_t)(kt + bRow) * DOUT + nBase + bC];
        As[aC + 0][aRow] = av.x;
        As[aC + 1][aRow] = av.y;
        As[aC + 2][aRow] = av.z;
        As[aC + 3][aRow] = av.w;
        *(float4*)&Bs[bRow][bC] = bv;
        __syncthreads();

        #pragma unroll
        for (int k = 0; k < 16; k++) {
            float4 a = *(const float4*)&As[k][ty * 4];
            float4 b = *(const float4*)&Bs[k][tx * 4];
            acc[0][0] += a.x * b.x; acc[0][1] += a.x * b.y; acc[0][2] += a.x * b.z; acc[0][3] += a.x * b.w;
            acc[1][0] += a.y * b.x; acc[1][1] += a.y * b.y; acc[1][2] += a.y * b.z; acc[1][3] += a.y * b.w;
            acc[2][0] += a.z * b.x; acc[2][1] += a.z * b.y; acc[2][2] += a.z * b.z; acc[2][3] += a.z * b.w;
            acc[3][0] += a.w * b.x; acc[3][1] += a.w * b.y; acc[3][2] += a.w * b.z; acc[3][3] += a.w * b.w;
        }
        __syncthreads();
    }

    const float4 bias = *(const float4*)&bo[nBase + tx * 4];
    #pragma unroll
    for (int i = 0; i < 4; i++) {
        int m = mBase + ty * 4 + i;
        float4 v = make_float4(acc[i][0] + bias.x, acc[i][1] + bias.y,
                               acc[i][2] + bias.z, acc[i][3] + bias.w);
        *(float4*)&out[(size_t)m * DOUT + nBase + tx * 4] = v;
    }
}

// ---------------------------------------------------------------------------
// Launch
// ---------------------------------------------------------------------------
extern "C" void kernel_launch(void* const* d_in, const int* in_sizes, int n_in,
                              void* d_out, int out_size)
{
    const float* x  = (const float*)d_in[0];
    const float* Wq = (const float*)d_in[1];
    const float* Wk = (const float*)d_in[2];
    const float* Wv = (const float*)d_in[3];
    const float* Wo = (const float*)d_in[4];
    const float* bo = (const float*)d_in[5];
    float* out = (float*)d_out;

    dim3 g1(MTOT / 64, DOUT / 64, 3);
    qkv_gemm_kernel<<<g1, 256>>>(x, Wq, Wk, Wv);

    dim3 g2(SEQ / 128, BATCH * NH);
    attn_kernel<<<g2, 128>>>();

    dim3 g3(MTOT / 64, DOUT / 64, 1);
    oproj_gemm_kernel<<<g3, 256>>>(Wo, bo, out);
}

// round 7
// speedup vs baseline: 1.9869x; 1.9869x over previous
#include <cuda_runtime.h>
#include <mma.h>
#include <stdint.h>
using namespace nvcuda;

// Problem constants
#define DIN   1024
#define DOUT  1024
#define NH    16
#define DH    64
#define BATCH 2
#define SEQ   2048
#define MTOT  (BATCH * SEQ)   // 4096 rows

// Scratch (allocation-free: __device__ globals)
__device__ float g_qkv[3ull * BATCH * NH * SEQ * DH];   // [3][B*H][T][DH]
__device__ float g_ctx[(size_t)BATCH * SEQ * DOUT];     // [B*T][DOUT] (tf32-rounded)
__device__ float g_wt [4ull * DIN * DOUT];              // [4][N][K] transposed, tf32-rounded
__device__ float g_xr [(size_t)MTOT * DIN];             // x, tf32-rounded

// ---------------------------------------------------------------------------
// Helpers
// ---------------------------------------------------------------------------
__device__ __forceinline__ uint32_t smem_u32(const void* p) {
    uint32_t a;
    asm("{ .reg .u64 t; cvta.to.shared.u64 t, %1; cvt.u32.u64 %0, t; }" : "=r"(a) : "l"(p));
    return a;
}
__device__ __forceinline__ float cvt_tf32_rn(float f) {
    uint32_t r;
    asm("cvt.rna.tf32.f32 %0, %1;" : "=r"(r) : "f"(f));
    return __uint_as_float(r);
}
#define CP_ASYNC16(dst_u32, src_ptr) \
    asm volatile("cp.async.cg.shared.global [%0], [%1], 16;" :: "r"(dst_u32), "l"(src_ptr))
#define CP_COMMIT() asm volatile("cp.async.commit_group;" ::: "memory")
#define CP_WAIT1()  asm volatile("cp.async.wait_group 1;" ::: "memory")
#define CP_WAIT0()  asm volatile("cp.async.wait_group 0;" ::: "memory")

// SMEM tile geometry: row stride 36 floats (144B, 16B-multiple, conflict-light)
#define STRIDE 36
#define ATILE  (128 * STRIDE)          // floats per (A or B) tile
#define SM_BUF (2 * ATILE)             // one double-buffer stage = A + B
#define SMEM_BYTES (2 * SM_BUF * 4)    // 73728 B

// ---------------------------------------------------------------------------
// Kernel 0a: transpose + tf32-round the 4 weight matrices into g_wt[w][n][k]
// ---------------------------------------------------------------------------
__global__ __launch_bounds__(256) void transpose_w_kernel(
    const float* __restrict__ Wq, const float* __restrict__ Wk,
    const float* __restrict__ Wv, const float* __restrict__ Wo)
{
    const int w = blockIdx.z;
    const float* W = (w == 0) ? Wq : (w == 1) ? Wk : (w == 2) ? Wv : Wo;
    float* Wt = g_wt + (size_t)w * DIN * DOUT;

    __shared__ float tile[32][33];
    const int tx = threadIdx.x & 31;
    const int ty = threadIdx.x >> 5;          // 0..7
    const int n0 = blockIdx.x * 32;
    const int k0 = blockIdx.y * 32;

    #pragma unroll
    for (int r = 0; r < 4; r++)
        tile[ty + r * 8][tx] = W[(size_t)(k0 + ty + r * 8) * DOUT + n0 + tx];
    __syncthreads();
    #pragma unroll
    for (int r = 0; r < 4; r++)
        Wt[(size_t)(n0 + ty + r * 8) * DIN + k0 + tx] = cvt_tf32_rn(tile[tx][ty + r * 8]);
}

// ---------------------------------------------------------------------------
// Kernel 0b: tf32-round x into g_xr
// ---------------------------------------------------------------------------
__global__ __launch_bounds__(256) void round_x_kernel(const float* __restrict__ x)
{
    const size_t i = ((size_t)blockIdx.x * 256 + threadIdx.x) * 4;
    float4 v = *(const float4*)(x + i);
    v.x = cvt_tf32_rn(v.x); v.y = cvt_tf32_rn(v.y);
    v.z = cvt_tf32_rn(v.z); v.w = cvt_tf32_rn(v.w);
    *(float4*)(g_xr + i) = v;
}

// ---------------------------------------------------------------------------
// wmma tf32 GEMM: C[128x128 tile] = A[M,1024] @ Wt^T  (Wt is [N][K])
// 256 threads = 8 warps (4 m x 2 n), warp tile 32x64, m16n16k8 fragments.
// MODE 0: QKV (A = g_xr, W = g_wt[blockIdx.z], out -> g_qkv head layout)
// MODE 1: O-proj (A = g_ctx, W = g_wt[3], out -> d_out raw; bias added later)
// ---------------------------------------------------------------------------
template <int MODE>
__global__ void __launch_bounds__(256, 2) gemm_tc_kernel(float* __restrict__ out)
{
    extern __shared__ float smem[];
    const int tid = threadIdx.x;
    const int wid = tid >> 5;
    const int warp_m = wid & 3;        // 0..3 -> 32-row slab
    const int warp_n = wid >> 2;       // 0..1 -> 64-col slab
    const int mBase = blockIdx.x * 128;
    const int nBase = blockIdx.y * 128;

    const float* A = (MODE == 0) ? g_xr : g_ctx;
    const float* B = g_wt + ((MODE == 0) ? (size_t)blockIdx.z : 3ull) * DIN * DOUT;

    // per-thread cp.async indices: i = tid + j*256 covers 1024 16B-chunks/tile
    const int r_  = tid >> 3;          // base row 0..31 (+32 per j)
    const int c4_ = tid & 7;           // 16B chunk within 32-float row

    wmma::fragment<wmma::accumulator, 16, 16, 8, float> acc[2][4];
    #pragma unroll
    for (int i = 0; i < 2; i++)
        #pragma unroll
        for (int j = 0; j < 4; j++) wmma::fill_fragment(acc[i][j], 0.0f);

    // issue cp.async for k-chunk kc into buffer buf
    auto issue = [&](int kc, int buf) {
        float* dstA = smem + buf * SM_BUF;
        float* dstB = dstA + ATILE;
        const float* srcA = A + (size_t)mBase * DIN + kc * 32;
        const float* srcB = B + (size_t)nBase * DIN + kc * 32;
        #pragma unroll
        for (int j = 0; j < 4; j++) {
            int r = r_ + j * 32;
            uint32_t da = smem_u32(dstA + r * STRIDE + c4_ * 4);
            CP_ASYNC16(da, srcA + (size_t)r * DIN + c4_ * 4);
            uint32_t db = smem_u32(dstB + r * STRIDE + c4_ * 4);
            CP_ASYNC16(db, srcB + (size_t)r * DIN + c4_ * 4);
        }
        CP_COMMIT();
    };

    issue(0, 0);
    for (int kc = 0; kc < 32; kc++) {
        const int buf = kc & 1;
        if (kc + 1 < 32) { issue(kc + 1, buf ^ 1); CP_WAIT1(); }
        else             { CP_WAIT0(); }
        __syncthreads();

        const float* As = smem + buf * SM_BUF;
        const float* Bs = As + ATILE;
        #pragma unroll
        for (int ks = 0; ks < 4; ks++) {
            wmma::fragment<wmma::matrix_a, 16, 16, 8, wmma::precision::tf32, wmma::row_major> af[2];
            wmma::fragment<wmma::matrix_b, 16, 16, 8, wmma::precision::tf32, wmma::col_major> bf[4];
            #pragma unroll
            for (int i = 0; i < 2; i++)
                wmma::load_matrix_sync(af[i], As + (warp_m * 32 + i * 16) * STRIDE + ks * 8, STRIDE);
            #pragma unroll
            for (int j = 0; j < 4; j++)
                wmma::load_matrix_sync(bf[j], Bs + (warp_n * 64 + j * 16) * STRIDE + ks * 8, STRIDE);
            #pragma unroll
            for (int i = 0; i < 2; i++)
                #pragma unroll
                for (int j = 0; j < 4; j++)
                    wmma::mma_sync(acc[i][j], af[i], bf[j], acc[i][j]);
        }
        __syncthreads();
    }

    // Epilogue
    #pragma unroll
    for (int i = 0; i < 2; i++) {
        #pragma unroll
        for (int j = 0; j < 4; j++) {
            const int m0 = mBase + warp_m * 32 + i * 16;
            const int nc = nBase + warp_n * 64 + j * 16;
            if (MODE == 0) {
                const int w = blockIdx.z;
                const int head = nc >> 6, dh0 = nc & 63;
                const int b = m0 >> 11, t0 = m0 & (SEQ - 1);
                float* p = g_qkv + ((((size_t)w * BATCH + b) * NH + head) * SEQ + t0) * DH + dh0;
                wmma::store_matrix_sync(p, acc[i][j], DH, wmma::mem_row_major);
            } else {
                float* p = out + (size_t)m0 * DOUT + nc;
                wmma::store_matrix_sync(p, acc[i][j], DOUT, wmma::mem_row_major);
            }
        }
    }
}

// ---------------------------------------------------------------------------
// Bias add for O-proj output (in place on d_out)
// ---------------------------------------------------------------------------
__global__ __launch_bounds__(256) void bias_add_kernel(const float* __restrict__ bo,
                                                       float* __restrict__ out)
{
    const int m = blockIdx.x;
    const int c = threadIdx.x * 4;
    float4 v = *(float4*)(out + (size_t)m * DOUT + c);
    float4 b = *(const float4*)(bo + c);
    v.x += b.x; v.y += b.y; v.z += b.z; v.w += b.w;
    *(float4*)(out + (size_t)m * DOUT + c) = v;
}

// ---------------------------------------------------------------------------
// Causal flash attention, fp32 (epilogue now tf32-rounds ctx for the O-proj)
// ---------------------------------------------------------------------------
__global__ __launch_bounds__(128) void attn_kernel()
{
    const size_t plane = (size_t)BATCH * NH * SEQ * DH;
    const float* Q = g_qkv;
    const float* K = g_qkv + plane;
    const float* V = g_qkv + 2 * plane;

    const int bh = blockIdx.y;
    const int qi = blockIdx.x * 128 + threadIdx.x;

    const float* Kbh = K + (size_t)bh * SEQ * DH;
    const float* Vbh = V + (size_t)bh * SEQ * DH;

    float q[DH];
    {
        const float* qptr = Q + ((size_t)bh * SEQ + qi) * DH;
        #pragma unroll
        for (int d = 0; d < DH; d++) q[d] = qptr[d] * 0.125f;
    }

    __shared__ float Ks[32][DH];
    __shared__ float Vs[32][DH];

    float accum[DH];
    #pragma unroll
    for (int d = 0; d < DH; d++) accum[d] = 0.0f;
    float m_run = -1e30f;
    float l_run = 0.0f;

    const int nkt = blockIdx.x * 4 + 4;

    for (int kt = 0; kt < nkt; kt++) {
        __syncthreads();
        {
            const float4* ksrc = (const float4*)(Kbh + (size_t)kt * 32 * DH);
            const float4* vsrc = (const float4*)(Vbh + (size_t)kt * 32 * DH);
            float4* kdst = (float4*)&Ks[0][0];
            float4* vdst = (float4*)&Vs[0][0];
            #pragma unroll
            for (int i = 0; i < 4; i++) {
                int idx = threadIdx.x + i * 128;
                kdst[idx] = ksrc[idx];
                vdst[idx] = vsrc[idx];
            }
        }
        __syncthreads();

        float s[32];
        #pragma unroll
        for (int j = 0; j < 32; j++) {
            const float4* krow = (const float4*)&Ks[j][0];
            float sum = 0.0f;
            #pragma unroll
            for (int d4 = 0; d4 < 16; d4++) {
                float4 kv = krow[d4];
                sum += q[d4 * 4 + 0] * kv.x;
                sum += q[d4 * 4 + 1] * kv.y;
                sum += q[d4 * 4 + 2] * kv.z;
                sum += q[d4 * 4 + 3] * kv.w;
            }
            s[j] = sum;
        }

        const int k0 = kt * 32;
        if (k0 + 31 > qi) {
            #pragma unroll
            for (int j = 0; j < 32; j++)
                if (k0 + j > qi) s[j] = -1e30f;
        }

        float tmax = -1e30f;
        #pragma unroll
        for (int j = 0; j < 32; j++) tmax = fmaxf(tmax, s[j]);

        if (tmax > -1e29f) {
            float m_new = fmaxf(m_run, tmax);
            float corr  = __expf(m_run - m_new);
            float psum  = 0.0f;
            #pragma unroll
            for (int j = 0; j < 32; j++) {
                s[j] = __expf(s[j] - m_new);
                psum += s[j];
            }
            l_run = l_run * corr + psum;
            #pragma unroll
            for (int d = 0; d < DH; d++) accum[d] *= corr;
            #pragma unroll
            for (int j = 0; j < 32; j++) {
                const float p = s[j];
                const float4* vrow = (const float4*)&Vs[j][0];
                #pragma unroll
                for (int d4 = 0; d4 < 16; d4++) {
                    float4 vv = vrow[d4];
                    accum[d4 * 4 + 0] += p * vv.x;
                    accum[d4 * 4 + 1] += p * vv.y;
                    accum[d4 * 4 + 2] += p * vv.z;
                    accum[d4 * 4 + 3] += p * vv.w;
                }
            }
            m_run = m_new;
        }
    }

    // Normalize, tf32-round (zero-mean rna), and write ctx[b][t][h*DH + d]
    const float inv = 1.0f / l_run;
    const int b = bh >> 4;
    const int h = bh & (NH - 1);
    float* outp = g_ctx + ((size_t)(b * SEQ + qi)) * DOUT + h * DH;
    #pragma unroll
    for (int d4 = 0; d4 < 16; d4++) {
        float4 v = make_float4(cvt_tf32_rn(accum[d4 * 4 + 0] * inv),
                               cvt_tf32_rn(accum[d4 * 4 + 1] * inv),
                               cvt_tf32_rn(accum[d4 * 4 + 2] * inv),
                               cvt_tf32_rn(accum[d4 * 4 + 3] * inv));
        *(float4*)&outp[d4 * 4] = v;
    }
}

// ---------------------------------------------------------------------------
// Launch
// ---------------------------------------------------------------------------
extern "C" void kernel_launch(void* const* d_in, const int* in_sizes, int n_in,
                              void* d_out, int out_size)
{
    const float* x  = (const float*)d_in[0];
    const float* Wq = (const float*)d_in[1];
    const float* Wk = (const float*)d_in[2];
    const float* Wv = (const float*)d_in[3];
    const float* Wo = (const float*)d_in[4];
    const float* bo = (const float*)d_in[5];
    float* out = (float*)d_out;

    cudaFuncSetAttribute(gemm_tc_kernel<0>, cudaFuncAttributeMaxDynamicSharedMemorySize, SMEM_BYTES);
    cudaFuncSetAttribute(gemm_tc_kernel<1>, cudaFuncAttributeMaxDynamicSharedMemorySize, SMEM_BYTES);

    dim3 gt(DOUT / 32, DIN / 32, 4);
    transpose_w_kernel<<<gt, 256>>>(Wq, Wk, Wv, Wo);

    round_x_kernel<<<(MTOT * DIN) / (256 * 4), 256>>>(x);

    dim3 g1(MTOT / 128, DOUT / 128, 3);
    gemm_tc_kernel<0><<<g1, 256, SMEM_BYTES>>>(nullptr);

    dim3 g2(SEQ / 128, BATCH * NH);
    attn_kernel<<<g2, 128>>>();

    dim3 g3(MTOT / 128, DOUT / 128, 1);
    gemm_tc_kernel<1><<<g3, 256, SMEM_BYTES>>>(out);

    bias_add_kernel<<<MTOT, 256>>>(bo, out);
}

// round 9
// speedup vs baseline: 2.6628x; 1.3402x over previous
#include <cuda_runtime.h>
#include <mma.h>
#include <stdint.h>
using namespace nvcuda;

// Problem constants
#define DIN   1024
#define DOUT  1024
#define NH    16
#define DH    64
#define BATCH 2
#define SEQ   2048
#define MTOT  (BATCH * SEQ)   // 4096 rows

// Scratch (allocation-free: __device__ globals)
__device__ float g_qkv[3ull * BATCH * NH * SEQ * DH];   // [3][B*H][T][DH], tf32-rounded
__device__ float g_ctx[(size_t)BATCH * SEQ * DOUT];     // [B*T][DOUT], tf32-rounded
__device__ float g_wt [4ull * DIN * DOUT];              // [4][N][K] transposed, tf32-rounded
__device__ float g_xr [(size_t)MTOT * DIN];             // x, tf32-rounded

// ---------------------------------------------------------------------------
// Helpers
// ---------------------------------------------------------------------------
__device__ __forceinline__ uint32_t smem_u32(const void* p) {
    uint32_t a;
    asm("{ .reg .u64 t; cvta.to.shared.u64 t, %1; cvt.u32.u64 %0, t; }" : "=r"(a) : "l"(p));
    return a;
}
__device__ __forceinline__ float cvt_tf32_rn(float f) {
    uint32_t r;
    asm("cvt.rna.tf32.f32 %0, %1;" : "=r"(r) : "f"(f));
    return __uint_as_float(r);
}
#define CP_ASYNC16(dst_u32, src_ptr) \
    asm volatile("cp.async.cg.shared.global [%0], [%1], 16;" :: "r"(dst_u32), "l"(src_ptr))
#define CP_COMMIT() asm volatile("cp.async.commit_group;" ::: "memory")
#define CP_WAIT1()  asm volatile("cp.async.wait_group 1;" ::: "memory")
#define CP_WAIT0()  asm volatile("cp.async.wait_group 0;" ::: "memory")

// ===========================================================================
// Projection GEMMs (unchanged from R7 except epilogue tf32 rounding in MODE 0)
// ===========================================================================
#define STRIDE 36
#define ATILE  (128 * STRIDE)
#define SM_BUF (2 * ATILE)
#define SMEM_BYTES (2 * SM_BUF * 4)

__global__ __launch_bounds__(256) void transpose_w_kernel(
    const float* __restrict__ Wq, const float* __restrict__ Wk,
    const float* __restrict__ Wv, const float* __restrict__ Wo)
{
    const int w = blockIdx.z;
    const float* W = (w == 0) ? Wq : (w == 1) ? Wk : (w == 2) ? Wv : Wo;
    float* Wt = g_wt + (size_t)w * DIN * DOUT;

    __shared__ float tile[32][33];
    const int tx = threadIdx.x & 31;
    const int ty = threadIdx.x >> 5;
    const int n0 = blockIdx.x * 32;
    const int k0 = blockIdx.y * 32;

    #pragma unroll
    for (int r = 0; r < 4; r++)
        tile[ty + r * 8][tx] = W[(size_t)(k0 + ty + r * 8) * DOUT + n0 + tx];
    __syncthreads();
    #pragma unroll
    for (int r = 0; r < 4; r++)
        Wt[(size_t)(n0 + ty + r * 8) * DIN + k0 + tx] = cvt_tf32_rn(tile[tx][ty + r * 8]);
}

__global__ __launch_bounds__(256) void round_x_kernel(const float* __restrict__ x)
{
    const size_t i = ((size_t)blockIdx.x * 256 + threadIdx.x) * 4;
    float4 v = *(const float4*)(x + i);
    v.x = cvt_tf32_rn(v.x); v.y = cvt_tf32_rn(v.y);
    v.z = cvt_tf32_rn(v.z); v.w = cvt_tf32_rn(v.w);
    *(float4*)(g_xr + i) = v;
}

template <int MODE>
__global__ void __launch_bounds__(256, 2) gemm_tc_kernel(float* __restrict__ out)
{
    extern __shared__ float smem[];
    const int tid = threadIdx.x;
    const int wid = tid >> 5;
    const int warp_m = wid & 3;
    const int warp_n = wid >> 2;
    const int mBase = blockIdx.x * 128;
    const int nBase = blockIdx.y * 128;

    const float* A = (MODE == 0) ? g_xr : g_ctx;
    const float* B = g_wt + ((MODE == 0) ? (size_t)blockIdx.z : 3ull) * DIN * DOUT;

    const int r_  = tid >> 3;
    const int c4_ = tid & 7;

    wmma::fragment<wmma::accumulator, 16, 16, 8, float> acc[2][4];
    #pragma unroll
    for (int i = 0; i < 2; i++)
        #pragma unroll
        for (int j = 0; j < 4; j++) wmma::fill_fragment(acc[i][j], 0.0f);

    auto issue = [&](int kc, int buf) {
        float* dstA = smem + buf * SM_BUF;
        float* dstB = dstA + ATILE;
        const float* srcA = A + (size_t)mBase * DIN + kc * 32;
        const float* srcB = B + (size_t)nBase * DIN + kc * 32;
        #pragma unroll
        for (int j = 0; j < 4; j++) {
            int r = r_ + j * 32;
            CP_ASYNC16(smem_u32(dstA + r * STRIDE + c4_ * 4), srcA + (size_t)r * DIN + c4_ * 4);
            CP_ASYNC16(smem_u32(dstB + r * STRIDE + c4_ * 4), srcB + (size_t)r * DIN + c4_ * 4);
        }
        CP_COMMIT();
    };

    issue(0, 0);
    for (int kc = 0; kc < 32; kc++) {
        const int buf = kc & 1;
        if (kc + 1 < 32) { issue(kc + 1, buf ^ 1); CP_WAIT1(); }
        else             { CP_WAIT0(); }
        __syncthreads();

        const float* As = smem + buf * SM_BUF;
        const float* Bs = As + ATILE;
        #pragma unroll
        for (int ks = 0; ks < 4; ks++) {
            wmma::fragment<wmma::matrix_a, 16, 16, 8, wmma::precision::tf32, wmma::row_major> af[2];
            wmma::fragment<wmma::matrix_b, 16, 16, 8, wmma::precision::tf32, wmma::col_major> bf[4];
            #pragma unroll
            for (int i = 0; i < 2; i++)
                wmma::load_matrix_sync(af[i], As + (warp_m * 32 + i * 16) * STRIDE + ks * 8, STRIDE);
            #pragma unroll
            for (int j = 0; j < 4; j++)
                wmma::load_matrix_sync(bf[j], Bs + (warp_n * 64 + j * 16) * STRIDE + ks * 8, STRIDE);
            #pragma unroll
            for (int i = 0; i < 2; i++)
                #pragma unroll
                for (int j = 0; j < 4; j++)
                    wmma::mma_sync(acc[i][j], af[i], bf[j], acc[i][j]);
        }
        __syncthreads();
    }

    #pragma unroll
    for (int i = 0; i < 2; i++) {
        #pragma unroll
        for (int j = 0; j < 4; j++) {
            const int m0 = mBase + warp_m * 32 + i * 16;
            const int nc = nBase + warp_n * 64 + j * 16;
            if (MODE == 0) {
                // round QKV outputs to tf32-rna so attention HMMA truncation is exact
                #pragma unroll
                for (int e = 0; e < acc[i][j].num_elements; e++)
                    acc[i][j].x[e] = cvt_tf32_rn(acc[i][j].x[e]);
                const int w = blockIdx.z;
                const int head = nc >> 6, dh0 = nc & 63;
                const int b = m0 >> 11, t0 = m0 & (SEQ - 1);
                float* p = g_qkv + ((((size_t)w * BATCH + b) * NH + head) * SEQ + t0) * DH + dh0;
                wmma::store_matrix_sync(p, acc[i][j], DH, wmma::mem_row_major);
            } else {
                float* p = out + (size_t)m0 * DOUT + nc;
                wmma::store_matrix_sync(p, acc[i][j], DOUT, wmma::mem_row_major);
            }
        }
    }
}

__global__ __launch_bounds__(256) void bias_add_kernel(const float* __restrict__ bo,
                                                       float* __restrict__ out)
{
    const int m = blockIdx.x;
    const int c = threadIdx.x * 4;
    float4 v = *(float4*)(out + (size_t)m * DOUT + c);
    float4 b = *(const float4*)(bo + c);
    v.x += b.x; v.y += b.y; v.z += b.z; v.w += b.w;
    *(float4*)(out + (size_t)m * DOUT + c) = v;
}

// ===========================================================================
// Flash attention on wmma tf32.
// Block: 256 threads (8 warps). Br=128 q-rows, Bc=64 keys/iter.
// grid = (SEQ/128, B*NH).
// Smem (floats): sQ[128x72] | sK[2][64x72] | sV[2][64x72] | sP[128x72] | sO[128x64]
// ===========================================================================
#define APAD 72
#define AQ_OFF   0
#define AK_OFF   9216            // 128*72
#define AV_OFF   (AK_OFF + 2*4608)
#define AP_OFF   (AV_OFF + 2*4608)
#define AO_OFF   (AP_OFF + 9216)
#define ATTN_SMEM_FLOATS (AO_OFF + 128*64)
#define ATTN_SMEM_BYTES  (ATTN_SMEM_FLOATS * 4)   // 180224 B

__global__ void __launch_bounds__(256, 1) attn_tc_kernel()
{
    extern __shared__ float sm[];
    const int tid = threadIdx.x;
    const int wid = tid >> 5;
    const int qt  = blockIdx.x;
    const int bh  = blockIdx.y;
    const int qBase = qt * 128;

    const size_t plane = (size_t)BATCH * NH * SEQ * DH;
    const float* Qg = g_qkv + (size_t)bh * SEQ * DH + (size_t)qBase * DH;
    const float* Kg = g_qkv + plane + (size_t)bh * SEQ * DH;
    const float* Vg = g_qkv + 2 * plane + (size_t)bh * SEQ * DH;

    float* sQ = sm + AQ_OFF;
    float* sKb[2] = { sm + AK_OFF, sm + AK_OFF + 4608 };
    float* sVb[2] = { sm + AV_OFF, sm + AV_OFF + 4608 };
    float* sP = sm + AP_OFF;
    float* sO = sm + AO_OFF;

    // Stage Q (already tf32-rounded; scaling folded into softmax exp base)
    #pragma unroll
    for (int j = 0; j < 8; j++) {
        int i = tid + j * 256;            // 2048 float4 chunks
        int r = i >> 4, c = (i & 15) * 4;
        *(float4*)(sQ + r * APAD + c) = *(const float4*)(Qg + r * 64 + c);
    }
    // Zero O accumulator
    #pragma unroll
    for (int j = 0; j < 8; j++)
        ((float4*)sO)[tid + j * 256] = make_float4(0.f, 0.f, 0.f, 0.f);

    // Row ownership for softmax / O-update: 2 threads per row (col halves)
    const int row  = tid >> 1;
    const int half = tid & 1;
    float m_run = -1e30f, l_run = 0.0f, corr_reg = 1.0f;
    const float SCALE2 = 0.125f * 1.44269504088896340736f;  // 1/sqrt(64) * log2(e)

    auto issueKV = [&](int kt, int buf) {
        const float* ksrc = Kg + (size_t)kt * 64 * 64;
        const float* vsrc = Vg + (size_t)kt * 64 * 64;
        float* kd = sKb[buf];
        float* vd = sVb[buf];
        #pragma unroll
        for (int j = 0; j < 4; j++) {
            int c = tid + j * 256;         // 1024 chunks per tile
            int r = c >> 4, c16 = (c & 15) * 4;
            CP_ASYNC16(smem_u32(kd + r * APAD + c16), ksrc + r * 64 + c16);
            CP_ASYNC16(smem_u32(vd + r * APAD + c16), vsrc + r * 64 + c16);
        }
        CP_COMMIT();
    };

    const int nkt = qt * 2 + 2;     // causal: key tiles covering qBase+127
    issueKV(0, 0);

    const int wr = wid * 16;        // warp's 16-row slab of the 128 q-rows

    for (int kt = 0; kt < nkt; kt++) {
        const int buf = kt & 1;
        if (kt + 1 < nkt) { issueKV(kt + 1, buf ^ 1); CP_WAIT1(); }
        else              { CP_WAIT0(); }
        __syncthreads();   // KV ready; prev iteration's sP reads done

        // ---- S = Q @ K^T  (warp: 16x64) ----
        {
            wmma::fragment<wmma::accumulator, 16, 16, 8, float> sacc[4];
            #pragma unroll
            for (int j = 0; j < 4; j++) wmma::fill_fragment(sacc[j], 0.0f);
            #pragma unroll
            for (int ks = 0; ks < 8; ks++) {
                wmma::fragment<wmma::matrix_a, 16, 16, 8, wmma::precision::tf32, wmma::row_major> a;
                wmma::load_matrix_sync(a, sQ + wr * APAD + ks * 8, APAD);
                #pragma unroll
                for (int j = 0; j < 4; j++) {
                    wmma::fragment<wmma::matrix_b, 16, 16, 8, wmma::precision::tf32, wmma::col_major> b;
                    wmma::load_matrix_sync(b, sKb[buf] + (j * 16) * APAD + ks * 8, APAD);
                    wmma::mma_sync(sacc[j], a, b, sacc[j]);
                }
            }
            #pragma unroll
            for (int j = 0; j < 4; j++)
                wmma::store_matrix_sync(sP + wr * APAD + j * 16, sacc[j], APAD, wmma::mem_row_major);
        }
        __syncthreads();

        // ---- online softmax (2 threads per row, 32 cols each) ----
        {
            const int kBase = kt * 64;
            const int qi = qBase + row;
            float* Sr = sP + row * APAD + half * 32;
            float sv[32];
            float tmax = -1e30f;
            #pragma unroll
            for (int c = 0; c < 32; c++) {
                int key = kBase + half * 32 + c;
                float s = (key <= qi) ? Sr[c] * SCALE2 : -1e30f;
                sv[c] = s;
                tmax = fmaxf(tmax, s);
            }
            tmax = fmaxf(tmax, __shfl_xor_sync(0xffffffffu, tmax, 1));
            float m_new = fmaxf(m_run, tmax);
            corr_reg = exp2f(m_run - m_new);
            float psum = 0.0f;
            #pragma unroll
            for (int c = 0; c < 32; c++) {
                float p = exp2f(sv[c] - m_new);
                psum += p;
                Sr[c] = cvt_tf32_rn(p);
            }
            psum += __shfl_xor_sync(0xffffffffu, psum, 1);
            l_run = l_run * corr_reg + psum;
            m_run = m_new;
        }
        __syncthreads();

        // ---- PV: tmp(16x64 per warp) = P @ V, stored back into sP rows ----
        {
            wmma::fragment<wmma::accumulator, 16, 16, 8, float> oacc[4];
            #pragma unroll
            for (int j = 0; j < 4; j++) wmma::fill_fragment(oacc[j], 0.0f);
            #pragma unroll
            for (int ks = 0; ks < 8; ks++) {
                wmma::fragment<wmma::matrix_a, 16, 16, 8, wmma::precision::tf32, wmma::row_major> a;
                wmma::load_matrix_sync(a, sP + wr * APAD + ks * 8, APAD);
                #pragma unroll
                for (int j = 0; j < 4; j++) {
                    wmma::fragment<wmma::matrix_b, 16, 16, 8, wmma::precision::tf32, wmma::row_major> b;
                    wmma::load_matrix_sync(b, sVb[buf] + (ks * 8) * APAD + j * 16, APAD);
                    wmma::mma_sync(oacc[j], a, b, oacc[j]);
                }
            }
            // warp writes only its own 16 rows (which it alone read as A) — no race
            #pragma unroll
            for (int j = 0; j < 4; j++)
                wmma::store_matrix_sync(sP + wr * APAD + j * 16, oacc[j], APAD, wmma::mem_row_major);
        }
        __syncthreads();

        // ---- O = O*corr + tmp ----
        {
            float* Or = sO + row * 64 + half * 32;
            float* Tr = sP + row * APAD + half * 32;
            #pragma unroll
            for (int c = 0; c < 32; c += 4) {
                float4 o = *(float4*)(Or + c);
                float4 t = *(float4*)(Tr + c);
                o.x = o.x * corr_reg + t.x;
                o.y = o.y * corr_reg + t.y;
                o.z = o.z * corr_reg + t.z;
                o.w = o.w * corr_reg + t.w;
                *(float4*)(Or + c) = o;
            }
        }
        // loop-top __syncthreads() separates this from next tile's S store
    }

    // ---- normalize + tf32-round + write ctx[b][t][h*DH+d] ----
    const int b = bh >> 4;
    const int h = bh & (NH - 1);
    const float inv = 1.0f / l_run;
    float* dst = g_ctx + ((size_t)(b * SEQ + qBase + row)) * DOUT + h * DH + half * 32;
    float* Or = sO + row * 64 + half * 32;
    #pragma unroll
    for (int c = 0; c < 32; c += 4) {
        float4 o = *(float4*)(Or + c);
        float4 v = make_float4(cvt_tf32_rn(o.x * inv), cvt_tf32_rn(o.y * inv),
                               cvt_tf32_rn(o.z * inv), cvt_tf32_rn(o.w * inv));
        *(float4*)(dst + c) = v;
    }
}

// ---------------------------------------------------------------------------
// Launch
// ---------------------------------------------------------------------------
extern "C" void kernel_launch(void* const* d_in, const int* in_sizes, int n_in,
                              void* d_out, int out_size)
{
    const float* x  = (const float*)d_in[0];
    const float* Wq = (const float*)d_in[1];
    const float* Wk = (const float*)d_in[2];
    const float* Wv = (const float*)d_in[3];
    const float* Wo = (const float*)d_in[4];
    const float* bo = (const float*)d_in[5];
    float* out = (float*)d_out;

    cudaFuncSetAttribute(gemm_tc_kernel<0>, cudaFuncAttributeMaxDynamicSharedMemorySize, SMEM_BYTES);
    cudaFuncSetAttribute(gemm_tc_kernel<1>, cudaFuncAttributeMaxDynamicSharedMemorySize, SMEM_BYTES);
    cudaFuncSetAttribute(attn_tc_kernel,    cudaFuncAttributeMaxDynamicSharedMemorySize, ATTN_SMEM_BYTES);

    dim3 gt(DOUT / 32, DIN / 32, 4);
    transpose_w_kernel<<<gt, 256>>>(Wq, Wk, Wv, Wo);

    round_x_kernel<<<(MTOT * DIN) / (256 * 4), 256>>>(x);

    dim3 g1(MTOT / 128, DOUT / 128, 3);
    gemm_tc_kernel<0><<<g1, 256, SMEM_BYTES>>>(nullptr);

    dim3 g2(SEQ / 128, BATCH * NH);
    attn_tc_kernel<<<g2, 256, ATTN_SMEM_BYTES>>>();

    dim3 g3(MTOT / 128, DOUT / 128, 1);
    gemm_tc_kernel<1><<<g3, 256, SMEM_BYTES>>>(out);

    bias_add_kernel<<<MTOT, 256>>>(bo, out);
}

// round 13
// speedup vs baseline: 4.4947x; 1.6880x over previous
#include <cuda_runtime.h>
#include <mma.h>
#include <stdint.h>
using namespace nvcuda;

// Problem constants
#define DIN   1024
#define DOUT  1024
#define NH    16
#define DH    64
#define BATCH 2
#define SEQ   2048
#define MTOT  (BATCH * SEQ)   // 4096 rows

// Scratch (allocation-free: __device__ globals)
__device__ float g_qkv[3ull * BATCH * NH * SEQ * DH];   // [3][B*H][T][DH], tf32-rounded
__device__ float g_ctx[(size_t)BATCH * SEQ * DOUT];     // [B*T][DOUT], tf32-rounded
__device__ float g_wt [4ull * DIN * DOUT];              // [4][N][K] transposed, tf32-rounded
__device__ float g_xr [(size_t)MTOT * DIN];             // x, tf32-rounded

// ---------------------------------------------------------------------------
// Helpers
// ---------------------------------------------------------------------------
__device__ __forceinline__ uint32_t smem_u32(const void* p) {
    uint32_t a;
    asm("{ .reg .u64 t; cvta.to.shared.u64 t, %1; cvt.u32.u64 %0, t; }" : "=r"(a) : "l"(p));
    return a;
}
__device__ __forceinline__ float cvt_tf32_rn(float f) {
    uint32_t r;
    asm("cvt.rna.tf32.f32 %0, %1;" : "=r"(r) : "f"(f));
    return __uint_as_float(r);
}
__device__ __forceinline__ uint32_t tf32_bits(float f) {
    uint32_t r;
    asm("cvt.rna.tf32.f32 %0, %1;" : "=r"(r) : "f"(f));
    return r;
}
#define CP_ASYNC16(dst_u32, src_ptr) \
    asm volatile("cp.async.cg.shared.global [%0], [%1], 16;" :: "r"(dst_u32), "l"(src_ptr))
#define CP_COMMIT() asm volatile("cp.async.commit_group;" ::: "memory")
#define CP_WAIT1()  asm volatile("cp.async.wait_group 1;" ::: "memory")
#define CP_WAIT0()  asm volatile("cp.async.wait_group 0;" ::: "memory")

// mma.sync m16n8k8 tf32: D = A@B + C (in place)
__device__ __forceinline__ void mma8(float c[4], const uint32_t a[4], uint32_t b0, uint32_t b1) {
    asm volatile("mma.sync.aligned.m16n8k8.row.col.f32.tf32.tf32.f32 "
        "{%0,%1,%2,%3}, {%4,%5,%6,%7}, {%8,%9}, {%0,%1,%2,%3};"
        : "+f"(c[0]), "+f"(c[1]), "+f"(c[2]), "+f"(c[3])
        : "r"(a[0]), "r"(a[1]), "r"(a[2]), "r"(a[3]), "r"(b0), "r"(b1));
}

// ===========================================================================
// Projection GEMMs (unchanged from R9)
// ===========================================================================
#define STRIDE 36
#define ATILE  (128 * STRIDE)
#define SM_BUF (2 * ATILE)
#define SMEM_BYTES (2 * SM_BUF * 4)

__global__ __launch_bounds__(256) void transpose_w_kernel(
    const float* __restrict__ Wq, const float* __restrict__ Wk,
    const float* __restrict__ Wv, const float* __restrict__ Wo)
{
    const int w = blockIdx.z;
    const float* W = (w == 0) ? Wq : (w == 1) ? Wk : (w == 2) ? Wv : Wo;
    float* Wt = g_wt + (size_t)w * DIN * DOUT;

    __shared__ float tile[32][33];
    const int tx = threadIdx.x & 31;
    const int ty = threadIdx.x >> 5;
    const int n0 = blockIdx.x * 32;
    const int k0 = blockIdx.y * 32;

    #pragma unroll
    for (int r = 0; r < 4; r++)
        tile[ty + r * 8][tx] = W[(size_t)(k0 + ty + r * 8) * DOUT + n0 + tx];
    __syncthreads();
    #pragma unroll
    for (int r = 0; r < 4; r++)
        Wt[(size_t)(n0 + ty + r * 8) * DIN + k0 + tx] = cvt_tf32_rn(tile[tx][ty + r * 8]);
}

__global__ __launch_bounds__(256) void round_x_kernel(const float* __restrict__ x)
{
    const size_t i = ((size_t)blockIdx.x * 256 + threadIdx.x) * 4;
    float4 v = *(const float4*)(x + i);
    v.x = cvt_tf32_rn(v.x); v.y = cvt_tf32_rn(v.y);
    v.z = cvt_tf32_rn(v.z); v.w = cvt_tf32_rn(v.w);
    *(float4*)(g_xr + i) = v;
}

template <int MODE>
__global__ void __launch_bounds__(256, 2) gemm_tc_kernel(float* __restrict__ out)
{
    extern __shared__ float smem[];
    const int tid = threadIdx.x;
    const int wid = tid >> 5;
    const int warp_m = wid & 3;
    const int warp_n = wid >> 2;
    const int mBase = blockIdx.x * 128;
    const int nBase = blockIdx.y * 128;

    const float* A = (MODE == 0) ? g_xr : g_ctx;
    const float* B = g_wt + ((MODE == 0) ? (size_t)blockIdx.z : 3ull) * DIN * DOUT;

    const int r_  = tid >> 3;
    const int c4_ = tid & 7;

    wmma::fragment<wmma::accumulator, 16, 16, 8, float> acc[2][4];
    #pragma unroll
    for (int i = 0; i < 2; i++)
        #pragma unroll
        for (int j = 0; j < 4; j++) wmma::fill_fragment(acc[i][j], 0.0f);

    auto issue = [&](int kc, int buf) {
        float* dstA = smem + buf * SM_BUF;
        float* dstB = dstA + ATILE;
        const float* srcA = A + (size_t)mBase * DIN + kc * 32;
        const float* srcB = B + (size_t)nBase * DIN + kc * 32;
        #pragma unroll
        for (int j = 0; j < 4; j++) {
            int r = r_ + j * 32;
            CP_ASYNC16(smem_u32(dstA + r * STRIDE + c4_ * 4), srcA + (size_t)r * DIN + c4_ * 4);
            CP_ASYNC16(smem_u32(dstB + r * STRIDE + c4_ * 4), srcB + (size_t)r * DIN + c4_ * 4);
        }
        CP_COMMIT();
    };

    issue(0, 0);
    for (int kc = 0; kc < 32; kc++) {
        const int buf = kc & 1;
        if (kc + 1 < 32) { issue(kc + 1, buf ^ 1); CP_WAIT1(); }
        else             { CP_WAIT0(); }
        __syncthreads();

        const float* As = smem + buf * SM_BUF;
        const float* Bs = As + ATILE;
        #pragma unroll
        for (int ks = 0; ks < 4; ks++) {
            wmma::fragment<wmma::matrix_a, 16, 16, 8, wmma::precision::tf32, wmma::row_major> af[2];
            wmma::fragment<wmma::matrix_b, 16, 16, 8, wmma::precision::tf32, wmma::col_major> bf[4];
            #pragma unroll
            for (int i = 0; i < 2; i++)
                wmma::load_matrix_sync(af[i], As + (warp_m * 32 + i * 16) * STRIDE + ks * 8, STRIDE);
            #pragma unroll
            for (int j = 0; j < 4; j++)
                wmma::load_matrix_sync(bf[j], Bs + (warp_n * 64 + j * 16) * STRIDE + ks * 8, STRIDE);
            #pragma unroll
            for (int i = 0; i < 2; i++)
                #pragma unroll
                for (int j = 0; j < 4; j++)
                    wmma::mma_sync(acc[i][j], af[i], bf[j], acc[i][j]);
        }
        __syncthreads();
    }

    #pragma unroll
    for (int i = 0; i < 2; i++) {
        #pragma unroll
        for (int j = 0; j < 4; j++) {
            const int m0 = mBase + warp_m * 32 + i * 16;
            const int nc = nBase + warp_n * 64 + j * 16;
            if (MODE == 0) {
                #pragma unroll
                for (int e = 0; e < acc[i][j].num_elements; e++)
                    acc[i][j].x[e] = cvt_tf32_rn(acc[i][j].x[e]);
                const int w = blockIdx.z;
                const int head = nc >> 6, dh0 = nc & 63;
                const int b = m0 >> 11, t0 = m0 & (SEQ - 1);
                float* p = g_qkv + ((((size_t)w * BATCH + b) * NH + head) * SEQ + t0) * DH + dh0;
                wmma::store_matrix_sync(p, acc[i][j], DH, wmma::mem_row_major);
            } else {
                float* p = out + (size_t)m0 * DOUT + nc;
                wmma::store_matrix_sync(p, acc[i][j], DOUT, wmma::mem_row_major);
            }
        }
    }
}

__global__ __launch_bounds__(256) void bias_add_kernel(const float* __restrict__ bo,
                                                       float* __restrict__ out)
{
    const int m = blockIdx.x;
    const int c = threadIdx.x * 4;
    float4 v = *(float4*)(out + (size_t)m * DOUT + c);
    float4 b = *(const float4*)(bo + c);
    v.x += b.x; v.y += b.y; v.z += b.z; v.w += b.w;
    *(float4*)(out + (size_t)m * DOUT + c) = v;
}

// ===========================================================================
// Flash attention, register-resident mma.sync m16n8k8 tf32.
// Block: 128 threads (4 warps); warp owns 32 q-rows (2 m16 tiles). Br=128, Bc=64.
// grid = (SEQ/128, B*NH).
// Smem: K double-buffered stride 68, V double-buffered stride 72.  (70KB -> 2 CTA/SM)
// ===========================================================================
#define KSTR 68
#define VSTR 72
#define AK_OFF   0
#define AV_OFF   (2 * 64 * KSTR)                 // floats
#define ATTN_SMEM_FLOATS (AV_OFF + 2 * 64 * VSTR)
#define ATTN_SMEM_BYTES  (ATTN_SMEM_FLOATS * 4)  // 71680 B

__global__ void __launch_bounds__(128, 2) attn_tc_kernel()
{
    extern __shared__ float sm[];
    float* sK0 = sm + AK_OFF;
    float* sK1 = sm + AK_OFF + 64 * KSTR;
    float* sV0 = sm + AV_OFF;
    float* sV1 = sm + AV_OFF + 64 * VSTR;

    const int tid  = threadIdx.x;
    const int wid  = tid >> 5;
    const int lane = tid & 31;
    const int gid  = lane >> 2;      // groupID (row within fragment)
    const int tig  = lane & 3;       // threadID_in_group
    const int qt   = blockIdx.x;
    const int bh   = blockIdx.y;
    const int qBase = qt * 128;
    const int wr    = wid * 32;      // warp's 32-row slab

    const size_t plane = (size_t)BATCH * NH * SEQ * DH;
    const float* Qg = g_qkv + (size_t)bh * SEQ * DH + (size_t)qBase * DH;
    const float* Kg = g_qkv + plane + (size_t)bh * SEQ * DH;
    const float* Vg = g_qkv + 2 * plane + (size_t)bh * SEQ * DH;

    // ---- Stage Q (128x64) through the K buffers, load A-fragments, free bufs ----
    #pragma unroll
    for (int j = 0; j < 16; j++) {
        int i = tid + j * 128;             // 2048 float4 chunks
        int r = i >> 4, c = (i & 15) * 4;
        float* dst = (r < 64) ? (sK0 + r * KSTR + c) : (sK1 + (r - 64) * KSTR + c);
        *(float4*)dst = *(const float4*)(Qg + r * 64 + c);
    }
    __syncthreads();

    uint32_t qa[2][8][4];
    #pragma unroll
    for (int mt = 0; mt < 2; mt++) {
        const int r0 = wr + mt * 16 + gid;
        const float* q0 = (r0 < 64) ? (sK0 + r0 * KSTR) : (sK1 + (r0 - 64) * KSTR);
        const float* q1 = (r0 + 8 < 64) ? (sK0 + (r0 + 8) * KSTR) : (sK1 + (r0 - 56) * KSTR);
        #pragma unroll
        for (int ks = 0; ks < 8; ks++) {
            qa[mt][ks][0] = *(const uint32_t*)(q0 + ks * 8 + tig);
            qa[mt][ks][1] = *(const uint32_t*)(q1 + ks * 8 + tig);
            qa[mt][ks][2] = *(const uint32_t*)(q0 + ks * 8 + tig + 4);
            qa[mt][ks][3] = *(const uint32_t*)(q1 + ks * 8 + tig + 4);
        }
    }
    __syncthreads();

    // ---- state ----
    float oc[2][8][4];
    #pragma unroll
    for (int mt = 0; mt < 2; mt++)
        #pragma unroll
        for (int jo = 0; jo < 8; jo++)
            #pragma unroll
            for (int e = 0; e < 4; e++) oc[mt][jo][e] = 0.0f;
    float m_run[2][2] = {{-1e30f, -1e30f}, {-1e30f, -1e30f}};
    float l_run[2][2] = {{0.f, 0.f}, {0.f, 0.f}};
    const float SCALE2 = 0.125f * 1.44269504088896340736f;   // 1/sqrt(64) * log2(e)

    auto issueKV = [&](int kt, int buf) {
        const float* ksrc = Kg + (size_t)kt * 64 * 64;
        const float* vsrc = Vg + (size_t)kt * 64 * 64;
        float* kd = buf ? sK1 : sK0;
        float* vd = buf ? sV1 : sV0;
        #pragma unroll
        for (int j = 0; j < 8; j++) {
            int i = tid + j * 128;          // 1024 chunks per tile
            int r = i >> 4, c = (i & 15) * 4;
            CP_ASYNC16(smem_u32(kd + r * KSTR + c), ksrc + r * 64 + c);
            CP_ASYNC16(smem_u32(vd + r * VSTR + c), vsrc + r * 64 + c);
        }
        CP_COMMIT();
    };

    const int nkt = qt * 2 + 2;     // causal tile count
    issueKV(0, 0);

    for (int kt = 0; kt < nkt; kt++) {
        const int buf = kt & 1;
        __syncthreads();   // all warps done with buf^1 (prev compute) before overwrite
        if (kt + 1 < nkt) { issueKV(kt + 1, buf ^ 1); CP_WAIT1(); }
        else              { CP_WAIT0(); }
        __syncthreads();   // kt's K/V visible to all threads

        const float* kb = buf ? sK1 : sK0;
        const float* vb = buf ? sV1 : sV0;

        // ---- S = Q @ K^T : per warp 32x64, sc[mt][j][4] ----
        float sc[2][8][4];
        #pragma unroll
        for (int mt = 0; mt < 2; mt++)
            #pragma unroll
            for (int j = 0; j < 8; j++)
                #pragma unroll
                for (int e = 0; e < 4; e++) sc[mt][j][e] = 0.0f;

        #pragma unroll
        for (int j = 0; j < 8; j++) {
            const float* krow = kb + (j * 8 + gid) * KSTR;
            #pragma unroll
            for (int ks = 0; ks < 8; ks++) {
                uint32_t b0 = *(const uint32_t*)(krow + ks * 8 + tig);
                uint32_t b1 = *(const uint32_t*)(krow + ks * 8 + tig + 4);
                mma8(sc[0][j], qa[0][ks], b0, b1);
                mma8(sc[1][j], qa[1][ks], b0, b1);
            }
        }

        // ---- online softmax on register fragments ----
        const int kBase = kt * 64;
        float corr[2][2];
        #pragma unroll
        for (int mt = 0; mt < 2; mt++) {
            #pragma unroll
            for (int rh = 0; rh < 2; rh++) {
                const int qi = qBase + wr + mt * 16 + gid + rh * 8;
                float tmax = -1e30f;
                #pragma unroll
                for (int j = 0; j < 8; j++) {
                    int key0 = kBase + j * 8 + 2 * tig;
                    float v0 = sc[mt][j][rh * 2 + 0];
                    float v1 = sc[mt][j][rh * 2 + 1];
                    v0 = (key0     <= qi) ? v0 * SCALE2 : -1e30f;
                    v1 = (key0 + 1 <= qi) ? v1 * SCALE2 : -1e30f;
                    sc[mt][j][rh * 2 + 0] = v0;
                    sc[mt][j][rh * 2 + 1] = v1;
                    tmax = fmaxf(tmax, fmaxf(v0, v1));
                }
                tmax = fmaxf(tmax, __shfl_xor_sync(0xffffffffu, tmax, 1));
                tmax = fmaxf(tmax, __shfl_xor_sync(0xffffffffu, tmax, 2));
                float m_new = fmaxf(m_run[mt][rh], tmax);
                float cr = exp2f(m_run[mt][rh] - m_new);
                corr[mt][rh] = cr;
                float psum = 0.0f;
                #pragma unroll
                for (int j = 0; j < 8; j++) {
                    float p0 = exp2f(sc[mt][j][rh * 2 + 0] - m_new);
                    float p1 = exp2f(sc[mt][j][rh * 2 + 1] - m_new);
                    sc[mt][j][rh * 2 + 0] = p0;
                    sc[mt][j][rh * 2 + 1] = p1;
                    psum += p0 + p1;
                }
                psum += __shfl_xor_sync(0xffffffffu, psum, 1);
                psum += __shfl_xor_sync(0xffffffffu, psum, 2);
                l_run[mt][rh] = l_run[mt][rh] * cr + psum;
                m_run[mt][rh] = m_new;
            }
        }
        // rescale O accumulators
        #pragma unroll
        for (int mt = 0; mt < 2; mt++)
            #pragma unroll
            for (int jo = 0; jo < 8; jo++) {
                oc[mt][jo][0] *= corr[mt][0];
                oc[mt][jo][1] *= corr[mt][0];
                oc[mt][jo][2] *= corr[mt][1];
                oc[mt][jo][3] *= corr[mt][1];
            }

        // ---- P(C-frag) -> A-frag via shfl, then O += P @ V ----
        const int src0 = (lane & ~3) | (tig >> 1);
        const int src1 = src0 + 2;
        const bool odd = (tig & 1);
        #pragma unroll
        for (int ks = 0; ks < 8; ks++) {
            uint32_t pa[2][4];
            #pragma unroll
            for (int mt = 0; mt < 2; mt++) {
                float c0 = sc[mt][ks][0], c1 = sc[mt][ks][1];
                float c2 = sc[mt][ks][2], c3 = sc[mt][ks][3];
                float v00 = __shfl_sync(0xffffffffu, c0, src0);
                float v01 = __shfl_sync(0xffffffffu, c1, src0);
                float v10 = __shfl_sync(0xffffffffu, c2, src0);
                float v11 = __shfl_sync(0xffffffffu, c3, src0);
                float v02 = __shfl_sync(0xffffffffu, c0, src1);
                float v03 = __shfl_sync(0xffffffffu, c1, src1);
                float v12 = __shfl_sync(0xffffffffu, c2, src1);
                float v13 = __shfl_sync(0xffffffffu, c3, src1);
                pa[mt][0] = tf32_bits(odd ? v01 : v00);
                pa[mt][1] = tf32_bits(odd ? v11 : v10);
                pa[mt][2] = tf32_bits(odd ? v03 : v02);
                pa[mt][3] = tf32_bits(odd ? v13 : v12);
            }
            const float* vr0 = vb + (ks * 8 + tig) * VSTR;
            const float* vr1 = vb + (ks * 8 + tig + 4) * VSTR;
            #pragma unroll
            for (int jo = 0; jo < 8; jo++) {
                uint32_t b0 = *(const uint32_t*)(vr0 + jo * 8 + gid);
                uint32_t b1 = *(const uint32_t*)(vr1 + jo * 8 + gid);
                mma8(oc[0][jo], pa[0], b0, b1);
                mma8(oc[1][jo], pa[1], b0, b1);
            }
        }
    }

    // ---- normalize + tf32-round + write ctx[b][t][h*DH + d] ----
    const int b = bh >> 4;
    const int h = bh & (NH - 1);
    #pragma unroll
    for (int mt = 0; mt < 2; mt++) {
        const float inv0 = 1.0f / l_run[mt][0];
        const float inv1 = 1.0f / l_run[mt][1];
        const int r0 = qBase + wr + mt * 16 + gid;
        float* d0 = g_ctx + ((size_t)(b * SEQ + r0)) * DOUT + h * DH;
        float* d1 = g_ctx + ((size_t)(b * SEQ + r0 + 8)) * DOUT + h * DH;
        #pragma unroll
        for (int jo = 0; jo < 8; jo++) {
            const int c0 = jo * 8 + 2 * tig;
            float2 w0 = make_float2(cvt_tf32_rn(oc[mt][jo][0] * inv0),
                                    cvt_tf32_rn(oc[mt][jo][1] * inv0));
            float2 w1 = make_float2(cvt_tf32_rn(oc[mt][jo][2] * inv1),
                                    cvt_tf32_rn(oc[mt][jo][3] * inv1));
            *(float2*)(d0 + c0) = w0;
            *(float2*)(d1 + c0) = w1;
        }
    }
}

// ---------------------------------------------------------------------------
// Launch
// ---------------------------------------------------------------------------
extern "C" void kernel_launch(void* const* d_in, const int* in_sizes, int n_in,
                              void* d_out, int out_size)
{
    const float* x  = (const float*)d_in[0];
    const float* Wq = (const float*)d_in[1];
    const float* Wk = (const float*)d_in[2];
    const float* Wv = (const float*)d_in[3];
    const float* Wo = (const float*)d_in[4];
    const float* bo = (const float*)d_in[5];
    float* out = (float*)d_out;

    cudaFuncSetAttribute(gemm_tc_kernel<0>, cudaFuncAttributeMaxDynamicSharedMemorySize, SMEM_BYTES);
    cudaFuncSetAttribute(gemm_tc_kernel<1>, cudaFuncAttributeMaxDynamicSharedMemorySize, SMEM_BYTES);
    cudaFuncSetAttribute(attn_tc_kernel,    cudaFuncAttributeMaxDynamicSharedMemorySize, ATTN_SMEM_BYTES);

    dim3 gt(DOUT / 32, DIN / 32, 4);
    transpose_w_kernel<<<gt, 256>>>(Wq, Wk, Wv, Wo);

    round_x_kernel<<<(MTOT * DIN) / (256 * 4), 256>>>(x);

    dim3 g1(MTOT / 128, DOUT / 128, 3);
    gemm_tc_kernel<0><<<g1, 256, SMEM_BYTES>>>(nullptr);

    dim3 g2(SEQ / 128, BATCH * NH);
    attn_tc_kernel<<<g2, 128, ATTN_SMEM_BYTES>>>();

    dim3 g3(MTOT / 128, DOUT / 128, 1);
    gemm_tc_kernel<1><<<g3, 256, SMEM_BYTES>>>(out);

    bias_add_kernel<<<MTOT, 256>>>(bo, out);
}

// round 16
// speedup vs baseline: 4.6166x; 1.0271x over previous
#include <cuda_runtime.h>
#include <mma.h>
#include <stdint.h>
using namespace nvcuda;

// Problem constants
#define DIN   1024
#define DOUT  1024
#define NH    16
#define DH    64
#define BATCH 2
#define SEQ   2048
#define MTOT  (BATCH * SEQ)   // 4096 rows

// Scratch (allocation-free: __device__ globals)
__device__ float g_qkv[3ull * BATCH * NH * SEQ * DH];   // [3][B*H][T][DH], tf32-rounded
__device__ float g_ctx[(size_t)BATCH * SEQ * DOUT];     // [B*T][DOUT], tf32-rounded
__device__ float g_wt [4ull * DIN * DOUT];              // [4][N][K] transposed, tf32-rounded

// ---------------------------------------------------------------------------
// Helpers
// ---------------------------------------------------------------------------
__device__ __forceinline__ uint32_t smem_u32(const void* p) {
    uint32_t a;
    asm("{ .reg .u64 t; cvta.to.shared.u64 t, %1; cvt.u32.u64 %0, t; }" : "=r"(a) : "l"(p));
    return a;
}
__device__ __forceinline__ float cvt_tf32_rn(float f) {
    uint32_t r;
    asm("cvt.rna.tf32.f32 %0, %1;" : "=r"(r) : "f"(f));
    return __uint_as_float(r);
}
__device__ __forceinline__ uint32_t tf32_bits(float f) {
    uint32_t r;
    asm("cvt.rna.tf32.f32 %0, %1;" : "=r"(r) : "f"(f));
    return r;
}
#define CP_ASYNC16(dst_u32, src_ptr) \
    asm volatile("cp.async.cg.shared.global [%0], [%1], 16;" :: "r"(dst_u32), "l"(src_ptr))
#define CP_COMMIT() asm volatile("cp.async.commit_group;" ::: "memory")
#define CP_WAIT1()  asm volatile("cp.async.wait_group 1;" ::: "memory")
#define CP_WAIT0()  asm volatile("cp.async.wait_group 0;" ::: "memory")

// mma.sync m16n8k8 tf32: D = A@B + C (in place)
__device__ __forceinline__ void mma8(float c[4], const uint32_t a[4], uint32_t b0, uint32_t b1) {
    asm volatile("mma.sync.aligned.m16n8k8.row.col.f32.tf32.tf32.f32 "
        "{%0,%1,%2,%3}, {%4,%5,%6,%7}, {%8,%9}, {%0,%1,%2,%3};"
        : "+f"(c[0]), "+f"(c[1]), "+f"(c[2]), "+f"(c[3])
        : "r"(a[0]), "r"(a[1]), "r"(a[2]), "r"(a[3]), "r"(b0), "r"(b1));
}

// ===========================================================================
// Projection GEMMs: 128x128 CTA tile, 8 warps (32x64 each), BK=32,
// 3-stage cp.async pipeline, ONE __syncthreads per K-chunk.
// ===========================================================================
#define STRIDE 36
#define TILE_FLOATS (128 * STRIDE)            // one 128x32 tile (padded)
#define STAGE_FLOATS (2 * TILE_FLOATS)        // A + B per stage
#define NSTAGE 3
#define SMEM_BYTES (NSTAGE * STAGE_FLOATS * 4)  // 110592 B -> 2 CTAs/SM

__global__ __launch_bounds__(256) void transpose_w_kernel(
    const float* __restrict__ Wq, const float* __restrict__ Wk,
    const float* __restrict__ Wv, const float* __restrict__ Wo)
{
    const int w = blockIdx.z;
    const float* W = (w == 0) ? Wq : (w == 1) ? Wk : (w == 2) ? Wv : Wo;
    float* Wt = g_wt + (size_t)w * DIN * DOUT;

    __shared__ float tile[32][33];
    const int tx = threadIdx.x & 31;
    const int ty = threadIdx.x >> 5;
    const int n0 = blockIdx.x * 32;
    const int k0 = blockIdx.y * 32;

    #pragma unroll
    for (int r = 0; r < 4; r++)
        tile[ty + r * 8][tx] = W[(size_t)(k0 + ty + r * 8) * DOUT + n0 + tx];
    __syncthreads();
    #pragma unroll
    for (int r = 0; r < 4; r++)
        Wt[(size_t)(n0 + ty + r * 8) * DIN + k0 + tx] = cvt_tf32_rn(tile[tx][ty + r * 8]);
}

// MODE 0: A = xin (raw fp32; A fragments rounded in-register), out -> g_qkv layout
// MODE 1: A = g_ctx (device global, resolved IN KERNEL; pre-rounded), out -> d_out
template <int MODE>
__global__ void __launch_bounds__(256, 2) gemm_tc_kernel(const float* __restrict__ xin,
                                                         float* __restrict__ out)
{
    extern __shared__ float smem[];
    const int tid = threadIdx.x;
    const int wid = tid >> 5;
    const int warp_m = wid & 3;
    const int warp_n = wid >> 2;
    const int mBase = blockIdx.x * 128;
    const int nBase = blockIdx.y * 128;

    // NOTE: device globals must be resolved in device code, never passed from host.
    const float* A = (MODE == 0) ? xin : g_ctx;
    const float* B = g_wt + ((MODE == 0) ? (size_t)blockIdx.z : 3ull) * DIN * DOUT;

    const int r_  = tid >> 3;      // 0..31
    const int c4_ = tid & 7;       // 16B chunk in 32-float row

    wmma::fragment<wmma::accumulator, 16, 16, 8, float> acc[2][4];
    #pragma unroll
    for (int i = 0; i < 2; i++)
        #pragma unroll
        for (int j = 0; j < 4; j++) wmma::fill_fragment(acc[i][j], 0.0f);

    auto issue = [&](int kc, int st) {
        float* dstA = smem + st * STAGE_FLOATS;
        float* dstB = dstA + TILE_FLOATS;
        const float* srcA = A + (size_t)mBase * DIN + kc * 32;
        const float* srcB = B + (size_t)nBase * DIN + kc * 32;
        #pragma unroll
        for (int j = 0; j < 4; j++) {
            int r = r_ + j * 32;
            CP_ASYNC16(smem_u32(dstA + r * STRIDE + c4_ * 4), srcA + (size_t)r * DIN + c4_ * 4);
            CP_ASYNC16(smem_u32(dstB + r * STRIDE + c4_ * 4), srcB + (size_t)r * DIN + c4_ * 4);
        }
        CP_COMMIT();
    };

    issue(0, 0);
    issue(1, 1);
    for (int kc = 0; kc < 32; kc++) {
        const int st = kc % 3;
        if (kc == 31) CP_WAIT0(); else CP_WAIT1();
        __syncthreads();                       // stage kc ready; stage kc-1 fully consumed
        if (kc + 2 < 32) issue(kc + 2, (kc + 2) % 3);   // overwrites stage kc-1: safe

        const float* As = smem + st * STAGE_FLOATS;
        const float* Bs = As + TILE_FLOATS;
        #pragma unroll
        for (int ks = 0; ks < 4; ks++) {
            wmma::fragment<wmma::matrix_a, 16, 16, 8, wmma::precision::tf32, wmma::row_major> af[2];
            wmma::fragment<wmma::matrix_b, 16, 16, 8, wmma::precision::tf32, wmma::col_major> bf[4];
            #pragma unroll
            for (int i = 0; i < 2; i++) {
                wmma::load_matrix_sync(af[i], As + (warp_m * 32 + i * 16) * STRIDE + ks * 8, STRIDE);
                if (MODE == 0) {
                    // x is raw fp32: round to tf32-rna in-register (layout-agnostic)
                    #pragma unroll
                    for (int e = 0; e < af[i].num_elements; e++)
                        af[i].x[e] = cvt_tf32_rn(af[i].x[e]);
                }
            }
            #pragma unroll
            for (int j = 0; j < 4; j++)
                wmma::load_matrix_sync(bf[j], Bs + (warp_n * 64 + j * 16) * STRIDE + ks * 8, STRIDE);
            #pragma unroll
            for (int i = 0; i < 2; i++)
                #pragma unroll
                for (int j = 0; j < 4; j++)
                    wmma::mma_sync(acc[i][j], af[i], bf[j], acc[i][j]);
        }
    }
    __syncthreads();

    #pragma unroll
    for (int i = 0; i < 2; i++) {
        #pragma unroll
        for (int j = 0; j < 4; j++) {
            const int m0 = mBase + warp_m * 32 + i * 16;
            const int nc = nBase + warp_n * 64 + j * 16;
            if (MODE == 0) {
                // round QKV outputs to tf32-rna so attention HMMA truncation is exact
                #pragma unroll
                for (int e = 0; e < acc[i][j].num_elements; e++)
                    acc[i][j].x[e] = cvt_tf32_rn(acc[i][j].x[e]);
                const int w = blockIdx.z;
                const int head = nc >> 6, dh0 = nc & 63;
                const int b = m0 >> 11, t0 = m0 & (SEQ - 1);
                float* p = g_qkv + ((((size_t)w * BATCH + b) * NH + head) * SEQ + t0) * DH + dh0;
                wmma::store_matrix_sync(p, acc[i][j], DH, wmma::mem_row_major);
            } else {
                float* p = out + (size_t)m0 * DOUT + nc;
                wmma::store_matrix_sync(p, acc[i][j], DOUT, wmma::mem_row_major);
            }
        }
    }
}

__global__ __launch_bounds__(256) void bias_add_kernel(const float* __restrict__ bo,
                                                       float* __restrict__ out)
{
    const int m = blockIdx.x;
    const int c = threadIdx.x * 4;
    float4 v = *(float4*)(out + (size_t)m * DOUT + c);
    float4 b = *(const float4*)(bo + c);
    v.x += b.x; v.y += b.y; v.z += b.z; v.w += b.w;
    *(float4*)(out + (size_t)m * DOUT + c) = v;
}

// ===========================================================================
// Flash attention, register-resident mma.sync m16n8k8 tf32.
// Block: 128 threads (4 warps); warp owns 32 q-rows. Br=128, Bc=64.
// Mask-skip: tiles kt < 2*qt are provably fully unmasked.
// ===========================================================================
#define KSTR 68
#define VSTR 72
#define AK_OFF   0
#define AV_OFF   (2 * 64 * KSTR)
#define ATTN_SMEM_FLOATS (AV_OFF + 2 * 64 * VSTR)
#define ATTN_SMEM_BYTES  (ATTN_SMEM_FLOATS * 4)   // 71680 B

__global__ void __launch_bounds__(128, 2) attn_tc_kernel()
{
    extern __shared__ float sm[];
    float* sK0 = sm + AK_OFF;
    float* sK1 = sm + AK_OFF + 64 * KSTR;
    float* sV0 = sm + AV_OFF;
    float* sV1 = sm + AV_OFF + 64 * VSTR;

    const int tid  = threadIdx.x;
    const int wid  = tid >> 5;
    const int lane = tid & 31;
    const int gid  = lane >> 2;
    const int tig  = lane & 3;
    const int qt   = blockIdx.x;
    const int bh   = blockIdx.y;
    const int qBase = qt * 128;
    const int wr    = wid * 32;

    const size_t plane = (size_t)BATCH * NH * SEQ * DH;
    const float* Qg = g_qkv + (size_t)bh * SEQ * DH + (size_t)qBase * DH;
    const float* Kg = g_qkv + plane + (size_t)bh * SEQ * DH;
    const float* Vg = g_qkv + 2 * plane + (size_t)bh * SEQ * DH;

    // Stage Q through the K buffers, load A-fragments, free buffers
    #pragma unroll
    for (int j = 0; j < 16; j++) {
        int i = tid + j * 128;
        int r = i >> 4, c = (i & 15) * 4;
        float* dst = (r < 64) ? (sK0 + r * KSTR + c) : (sK1 + (r - 64) * KSTR + c);
        *(float4*)dst = *(const float4*)(Qg + r * 64 + c);
    }
    __syncthreads();

    uint32_t qa[2][8][4];
    #pragma unroll
    for (int mt = 0; mt < 2; mt++) {
        const int r0 = wr + mt * 16 + gid;
        const float* q0 = (r0 < 64) ? (sK0 + r0 * KSTR) : (sK1 + (r0 - 64) * KSTR);
        const float* q1 = (r0 + 8 < 64) ? (sK0 + (r0 + 8) * KSTR) : (sK1 + (r0 - 56) * KSTR);
        #pragma unroll
        for (int ks = 0; ks < 8; ks++) {
            qa[mt][ks][0] = *(const uint32_t*)(q0 + ks * 8 + tig);
            qa[mt][ks][1] = *(const uint32_t*)(q1 + ks * 8 + tig);
            qa[mt][ks][2] = *(const uint32_t*)(q0 + ks * 8 + tig + 4);
            qa[mt][ks][3] = *(const uint32_t*)(q1 + ks * 8 + tig + 4);
        }
    }
    __syncthreads();

    float oc[2][8][4];
    #pragma unroll
    for (int mt = 0; mt < 2; mt++)
        #pragma unroll
        for (int jo = 0; jo < 8; jo++)
            #pragma unroll
            for (int e = 0; e < 4; e++) oc[mt][jo][e] = 0.0f;
    float m_run[2][2] = {{-1e30f, -1e30f}, {-1e30f, -1e30f}};
    float l_run[2][2] = {{0.f, 0.f}, {0.f, 0.f}};
    const float SCALE2 = 0.125f * 1.44269504088896340736f;

    auto issueKV = [&](int kt, int buf) {
        const float* ksrc = Kg + (size_t)kt * 64 * 64;
        const float* vsrc = Vg + (size_t)kt * 64 * 64;
        float* kd = buf ? sK1 : sK0;
        float* vd = buf ? sV1 : sV0;
        #pragma unroll
        for (int j = 0; j < 8; j++) {
            int i = tid + j * 128;
            int r = i >> 4, c = (i & 15) * 4;
            CP_ASYNC16(smem_u32(kd + r * KSTR + c), ksrc + r * 64 + c);
            CP_ASYNC16(smem_u32(vd + r * VSTR + c), vsrc + r * 64 + c);
        }
        CP_COMMIT();
    };

    const int nkt = qt * 2 + 2;
    issueKV(0, 0);

    for (int kt = 0; kt < nkt; kt++) {
        const int buf = kt & 1;
        __syncthreads();
        if (kt + 1 < nkt) { issueKV(kt + 1, buf ^ 1); CP_WAIT1(); }
        else              { CP_WAIT0(); }
        __syncthreads();

        const float* kb = buf ? sK1 : sK0;
        const float* vb = buf ? sV1 : sV0;

        // ---- S = Q @ K^T ----
        float sc[2][8][4];
        #pragma unroll
        for (int mt = 0; mt < 2; mt++)
            #pragma unroll
            for (int j = 0; j < 8; j++)
                #pragma unroll
                for (int e = 0; e < 4; e++) sc[mt][j][e] = 0.0f;

        #pragma unroll
        for (int j = 0; j < 8; j++) {
            const float* krow = kb + (j * 8 + gid) * KSTR;
            #pragma unroll
            for (int ks = 0; ks < 8; ks++) {
                uint32_t b0 = *(const uint32_t*)(krow + ks * 8 + tig);
                uint32_t b1 = *(const uint32_t*)(krow + ks * 8 + tig + 4);
                mma8(sc[0][j], qa[0][ks], b0, b1);
                mma8(sc[1][j], qa[1][ks], b0, b1);
            }
        }

        // ---- online softmax on register fragments ----
        const int kBase = kt * 64;
        const bool needMask = (kt >= 2 * qt);   // only tiles straddling the diagonal
        float corr[2][2];
        #pragma unroll
        for (int mt = 0; mt < 2; mt++) {
            #pragma unroll
            for (int rh = 0; rh < 2; rh++) {
                const int qi = qBase + wr + mt * 16 + gid + rh * 8;
                float tmax = -1e30f;
                if (needMask) {
                    #pragma unroll
                    for (int j = 0; j < 8; j++) {
                        int key0 = kBase + j * 8 + 2 * tig;
                        float v0 = sc[mt][j][rh * 2 + 0];
                        float v1 = sc[mt][j][rh * 2 + 1];
                        v0 = (key0     <= qi) ? v0 * SCALE2 : -1e30f;
                        v1 = (key0 + 1 <= qi) ? v1 * SCALE2 : -1e30f;
                        sc[mt][j][rh * 2 + 0] = v0;
                        sc[mt][j][rh * 2 + 1] = v1;
                        tmax = fmaxf(tmax, fmaxf(v0, v1));
                    }
                } else {
                    #pragma unroll
                    for (int j = 0; j < 8; j++) {
                        float v0 = sc[mt][j][rh * 2 + 0] * SCALE2;
                        float v1 = sc[mt][j][rh * 2 + 1] * SCALE2;
                        sc[mt][j][rh * 2 + 0] = v0;
                        sc[mt][j][rh * 2 + 1] = v1;
                        tmax = fmaxf(tmax, fmaxf(v0, v1));
                    }
                }
                tmax = fmaxf(tmax, __shfl_xor_sync(0xffffffffu, tmax, 1));
                tmax = fmaxf(tmax, __shfl_xor_sync(0xffffffffu, tmax, 2));
                float m_new = fmaxf(m_run[mt][rh], tmax);
                float cr = exp2f(m_run[mt][rh] - m_new);
                corr[mt][rh] = cr;
                float psum = 0.0f;
                #pragma unroll
                for (int j = 0; j < 8; j++) {
                    float p0 = exp2f(sc[mt][j][rh * 2 + 0] - m_new);
                    float p1 = exp2f(sc[mt][j][rh * 2 + 1] - m_new);
                    sc[mt][j][rh * 2 + 0] = p0;
                    sc[mt][j][rh * 2 + 1] = p1;
                    psum += p0 + p1;
                }
                psum += __shfl_xor_sync(0xffffffffu, psum, 1);
                psum += __shfl_xor_sync(0xffffffffu, psum, 2);
                l_run[mt][rh] = l_run[mt][rh] * cr + psum;
                m_run[mt][rh] = m_new;
            }
        }
        #pragma unroll
        for (int mt = 0; mt < 2; mt++)
            #pragma unroll
            for (int jo = 0; jo < 8; jo++) {
                oc[mt][jo][0] *= corr[mt][0];
                oc[mt][jo][1] *= corr[mt][0];
                oc[mt][jo][2] *= corr[mt][1];
                oc[mt][jo][3] *= corr[mt][1];
            }

        // ---- P(C-frag) -> A-frag via shfl, then O += P @ V ----
        const int src0 = (lane & ~3) | (tig >> 1);
        const int src1 = src0 + 2;
        const bool odd = (tig & 1);
        #pragma unroll
        for (int ks = 0; ks < 8; ks++) {
            uint32_t pa[2][4];
            #pragma unroll
            for (int mt = 0; mt < 2; mt++) {
                float c0 = sc[mt][ks][0], c1 = sc[mt][ks][1];
                float c2 = sc[mt][ks][2], c3 = sc[mt][ks][3];
                float v00 = __shfl_sync(0xffffffffu, c0, src0);
                float v01 = __shfl_sync(0xffffffffu, c1, src0);
                float v10 = __shfl_sync(0xffffffffu, c2, src0);
                float v11 = __shfl_sync(0xffffffffu, c3, src0);
                float v02 = __shfl_sync(0xffffffffu, c0, src1);
                float v03 = __shfl_sync(0xffffffffu, c1, src1);
                float v12 = __shfl_sync(0xffffffffu, c2, src1);
                float v13 = __shfl_sync(0xffffffffu, c3, src1);
                pa[mt][0] = tf32_bits(odd ? v01 : v00);
                pa[mt][1] = tf32_bits(odd ? v11 : v10);
                pa[mt][2] = tf32_bits(odd ? v03 : v02);
                pa[mt][3] = tf32_bits(odd ? v13 : v12);
            }
            const float* vr0 = vb + (ks * 8 + tig) * VSTR;
            const float* vr1 = vb + (ks * 8 + tig + 4) * VSTR;
            #pragma unroll
            for (int jo = 0; jo < 8; jo++) {
                uint32_t b0 = *(const uint32_t*)(vr0 + jo * 8 + gid);
                uint32_t b1 = *(const uint32_t*)(vr1 + jo * 8 + gid);
                mma8(oc[0][jo], pa[0], b0, b1);
                mma8(oc[1][jo], pa[1], b0, b1);
            }
        }
    }

    // ---- normalize + tf32-round + write ctx ----
    const int b = bh >> 4;
    const int h = bh & (NH - 1);
    #pragma unroll
    for (int mt = 0; mt < 2; mt++) {
        const float inv0 = 1.0f / l_run[mt][0];
        const float inv1 = 1.0f / l_run[mt][1];
        const int r0 = qBase + wr + mt * 16 + gid;
        float* d0 = g_ctx + ((size_t)(b * SEQ + r0)) * DOUT + h * DH;
        float* d1 = g_ctx + ((size_t)(b * SEQ + r0 + 8)) * DOUT + h * DH;
        #pragma unroll
        for (int jo = 0; jo < 8; jo++) {
            const int c0 = jo * 8 + 2 * tig;
            float2 w0 = make_float2(cvt_tf32_rn(oc[mt][jo][0] * inv0),
                                    cvt_tf32_rn(oc[mt][jo][1] * inv0));
            float2 w1 = make_float2(cvt_tf32_rn(oc[mt][jo][2] * inv1),
                                    cvt_tf32_rn(oc[mt][jo][3] * inv1));
            *(float2*)(d0 + c0) = w0;
            *(float2*)(d1 + c0) = w1;
        }
    }
}

// ---------------------------------------------------------------------------
// Launch
// ---------------------------------------------------------------------------
extern "C" void kernel_launch(void* const* d_in, const int* in_sizes, int n_in,
                              void* d_out, int out_size)
{
    const float* x  = (const float*)d_in[0];
    const float* Wq = (const float*)d_in[1];
    const float* Wk = (const float*)d_in[2];
    const float* Wv = (const float*)d_in[3];
    const float* Wo = (const float*)d_in[4];
    const float* bo = (const float*)d_in[5];
    float* out = (float*)d_out;

    cudaFuncSetAttribute(gemm_tc_kernel<0>, cudaFuncAttributeMaxDynamicSharedMemorySize, SMEM_BYTES);
    cudaFuncSetAttribute(gemm_tc_kernel<1>, cudaFuncAttributeMaxDynamicSharedMemorySize, SMEM_BYTES);
    cudaFuncSetAttribute(attn_tc_kernel,    cudaFuncAttributeMaxDynamicSharedMemorySize, ATTN_SMEM_BYTES);

    dim3 gt(DOUT / 32, DIN / 32, 4);
    transpose_w_kernel<<<gt, 256>>>(Wq, Wk, Wv, Wo);

    dim3 g1(MTOT / 128, DOUT / 128, 3);
    gemm_tc_kernel<0><<<g1, 256, SMEM_BYTES>>>(x, nullptr);

    dim3 g2(SEQ / 128, BATCH * NH);
    attn_tc_kernel<<<g2, 128, ATTN_SMEM_BYTES>>>();

    dim3 g3(MTOT / 128, DOUT / 128, 1);
    gemm_tc_kernel<1><<<g3, 256, SMEM_BYTES>>>(nullptr, out);  // A = g_ctx resolved in-kernel

    bias_add_kernel<<<MTOT, 256>>>(bo, out);
}

// round 17
// speedup vs baseline: 7.5256x; 1.6301x over previous
#include <cuda_runtime.h>
#include <stdint.h>

// Problem constants
#define DIN   1024
#define DOUT  1024
#define NH    16
#define DH    64
#define BATCH 2
#define SEQ   2048
#define MTOT  (BATCH * SEQ)   // 4096 rows

// Scratch (allocation-free: __device__ globals)
__device__ float g_qkv[3ull * BATCH * NH * SEQ * DH];   // [3][B*H][T][DH], tf32-rounded
__device__ float g_ctx[(size_t)BATCH * SEQ * DOUT];     // [B*T][DOUT], tf32-rounded
__device__ float g_wt [4ull * DIN * DOUT];              // [4][N][K] transposed, tf32-rounded

// ---------------------------------------------------------------------------
// Helpers
// ---------------------------------------------------------------------------
__device__ __forceinline__ uint32_t smem_u32(const void* p) {
    uint32_t a;
    asm("{ .reg .u64 t; cvta.to.shared.u64 t, %1; cvt.u32.u64 %0, t; }" : "=r"(a) : "l"(p));
    return a;
}
__device__ __forceinline__ float cvt_tf32_rn(float f) {
    uint32_t r;
    asm("cvt.rna.tf32.f32 %0, %1;" : "=r"(r) : "f"(f));
    return __uint_as_float(r);
}
__device__ __forceinline__ uint32_t tf32_bits(float f) {
    uint32_t r;
    asm("cvt.rna.tf32.f32 %0, %1;" : "=r"(r) : "f"(f));
    return r;
}
#define CP_ASYNC16(dst_u32, src_ptr) \
    asm volatile("cp.async.cg.shared.global [%0], [%1], 16;" :: "r"(dst_u32), "l"(src_ptr))
#define CP_COMMIT() asm volatile("cp.async.commit_group;" ::: "memory")
#define CP_WAIT1()  asm volatile("cp.async.wait_group 1;" ::: "memory")
#define CP_WAIT0()  asm volatile("cp.async.wait_group 0;" ::: "memory")

// mma.sync m16n8k8 tf32: D = A@B + C (in place)
__device__ __forceinline__ void mma8(float c[4], const uint32_t a[4], uint32_t b0, uint32_t b1) {
    asm volatile("mma.sync.aligned.m16n8k8.row.col.f32.tf32.tf32.f32 "
        "{%0,%1,%2,%3}, {%4,%5,%6,%7}, {%8,%9}, {%0,%1,%2,%3};"
        : "+f"(c[0]), "+f"(c[1]), "+f"(c[2]), "+f"(c[3])
        : "r"(a[0]), "r"(a[1]), "r"(a[2]), "r"(a[3]), "r"(b0), "r"(b1));
}

// ===========================================================================
// Projection GEMMs: 128x128 CTA tile, 4 warps, warp tile 64x64 (manual mma8),
// BK=32, 3-stage cp.async pipeline, ONE __syncthreads per K-chunk.
// Per ks-step per warp: 16 A-LDS + 16 B-LDS feed 32 mma8 (HMMA-bound).
// ===========================================================================
#define STRIDE 36
#define TILE_FLOATS (128 * STRIDE)            // one 128x32 tile (padded)
#define STAGE_FLOATS (2 * TILE_FLOATS)        // A + B per stage
#define NSTAGE 3
#define SMEM_BYTES (NSTAGE * STAGE_FLOATS * 4)  // 110592 B -> 2 CTAs/SM

__global__ __launch_bounds__(256) void transpose_w_kernel(
    const float* __restrict__ Wq, const float* __restrict__ Wk,
    const float* __restrict__ Wv, const float* __restrict__ Wo)
{
    const int w = blockIdx.z;
    const float* W = (w == 0) ? Wq : (w == 1) ? Wk : (w == 2) ? Wv : Wo;
    float* Wt = g_wt + (size_t)w * DIN * DOUT;

    __shared__ float tile[32][33];
    const int tx = threadIdx.x & 31;
    const int ty = threadIdx.x >> 5;
    const int n0 = blockIdx.x * 32;
    const int k0 = blockIdx.y * 32;

    #pragma unroll
    for (int r = 0; r < 4; r++)
        tile[ty + r * 8][tx] = W[(size_t)(k0 + ty + r * 8) * DOUT + n0 + tx];
    __syncthreads();
    #pragma unroll
    for (int r = 0; r < 4; r++)
        Wt[(size_t)(n0 + ty + r * 8) * DIN + k0 + tx] = cvt_tf32_rn(tile[tx][ty + r * 8]);
}

// MODE 0: A = xin (raw fp32; A regs rounded after LDS), out -> g_qkv layout
// MODE 1: A = g_ctx (resolved IN KERNEL; pre-rounded), out -> d_out, bias fused
template <int MODE>
__global__ void __launch_bounds__(128, 2) gemm_tc_kernel(const float* __restrict__ xin,
                                                         const float* __restrict__ bo,
                                                         float* __restrict__ out)
{
    extern __shared__ float smem[];
    const int tid  = threadIdx.x;
    const int wid  = tid >> 5;
    const int lane = tid & 31;
    const int gid  = lane >> 2;    // 0..7
    const int tig  = lane & 3;     // 0..3
    const int warp_m = wid & 1;    // 2 warps in M (64 rows each)
    const int warp_n = wid >> 1;   // 2 warps in N (64 cols each)
    const int mBase = blockIdx.x * 128;
    const int nBase = blockIdx.y * 128;

    const float* A = (MODE == 0) ? xin : g_ctx;
    const float* B = g_wt + ((MODE == 0) ? (size_t)blockIdx.z : 3ull) * DIN * DOUT;

    const int r_  = tid >> 3;      // 0..15 (staging row base)
    const int c4_ = tid & 7;       // 16B chunk in 32-float row

    // acc[mt][n8][4]: warp tile 64x64 = 4 m16 x 8 n8
    float acc[4][8][4];
    #pragma unroll
    for (int mt = 0; mt < 4; mt++)
        #pragma unroll
        for (int n8 = 0; n8 < 8; n8++)
            #pragma unroll
            for (int e = 0; e < 4; e++) acc[mt][n8][e] = 0.0f;

    auto issue = [&](int kc, int st) {
        float* dstA = smem + st * STAGE_FLOATS;
        float* dstB = dstA + TILE_FLOATS;
        const float* srcA = A + (size_t)mBase * DIN + kc * 32;
        const float* srcB = B + (size_t)nBase * DIN + kc * 32;
        #pragma unroll
        for (int j = 0; j < 8; j++) {
            int r = r_ + j * 16;
            CP_ASYNC16(smem_u32(dstA + r * STRIDE + c4_ * 4), srcA + (size_t)r * DIN + c4_ * 4);
            CP_ASYNC16(smem_u32(dstB + r * STRIDE + c4_ * 4), srcB + (size_t)r * DIN + c4_ * 4);
        }
        CP_COMMIT();
    };

    issue(0, 0);
    issue(1, 1);
    for (int kc = 0; kc < 32; kc++) {
        const int st = kc % 3;
        if (kc == 31) CP_WAIT0(); else CP_WAIT1();
        __syncthreads();                       // stage kc ready; stage kc-1 fully consumed
        if (kc + 2 < 32) issue(kc + 2, (kc + 2) % 3);   // overwrites stage kc-1: safe

        const float* As = smem + st * STAGE_FLOATS;
        const float* Bs = As + TILE_FLOATS;
        #pragma unroll
        for (int ks = 0; ks < 4; ks++) {
            // A fragments for 4 m16 tiles (rows warp_m*64 + mt*16 + gid / +8)
            uint32_t af[4][4];
            #pragma unroll
            for (int mt = 0; mt < 4; mt++) {
                const float* a0 = As + (warp_m * 64 + mt * 16 + gid) * STRIDE + ks * 8;
                const float* a1 = a0 + 8 * STRIDE;
                if (MODE == 0) {
                    af[mt][0] = tf32_bits(a0[tig]);
                    af[mt][1] = tf32_bits(a1[tig]);
                    af[mt][2] = tf32_bits(a0[tig + 4]);
                    af[mt][3] = tf32_bits(a1[tig + 4]);
                } else {
                    af[mt][0] = *(const uint32_t*)(a0 + tig);
                    af[mt][1] = *(const uint32_t*)(a1 + tig);
                    af[mt][2] = *(const uint32_t*)(a0 + tig + 4);
                    af[mt][3] = *(const uint32_t*)(a1 + tig + 4);
                }
            }
            // B fragments: Bs is [n][k] row-major (same pattern as attention K)
            #pragma unroll
            for (int n8 = 0; n8 < 8; n8++) {
                const float* brow = Bs + (warp_n * 64 + n8 * 8 + gid) * STRIDE + ks * 8;
                uint32_t b0 = *(const uint32_t*)(brow + tig);
                uint32_t b1 = *(const uint32_t*)(brow + tig + 4);
                #pragma unroll
                for (int mt = 0; mt < 4; mt++)
                    mma8(acc[mt][n8], af[mt], b0, b1);
            }
        }
    }

    // ---- Epilogue: per-thread float2 stores ----
    #pragma unroll
    for (int mt = 0; mt < 4; mt++) {
        const int m0 = mBase + warp_m * 64 + mt * 16 + gid;   // row for c0,c1
        const int m1 = m0 + 8;                                 // row for c2,c3
        #pragma unroll
        for (int n8 = 0; n8 < 8; n8++) {
            const int col = nBase + warp_n * 64 + n8 * 8 + 2 * tig;
            if (MODE == 0) {
                const int w = blockIdx.z;
                const int head = col >> 6, dh0 = col & 63;
                const int b0i = m0 >> 11, t0 = m0 & (SEQ - 1);
                const int b1i = m1 >> 11, t1 = m1 & (SEQ - 1);
                float* p0 = g_qkv + ((((size_t)w * BATCH + b0i) * NH + head) * SEQ + t0) * DH + dh0;
                float* p1 = g_qkv + ((((size_t)w * BATCH + b1i) * NH + head) * SEQ + t1) * DH + dh0;
                *(float2*)p0 = make_float2(cvt_tf32_rn(acc[mt][n8][0]), cvt_tf32_rn(acc[mt][n8][1]));
                *(float2*)p1 = make_float2(cvt_tf32_rn(acc[mt][n8][2]), cvt_tf32_rn(acc[mt][n8][3]));
            } else {
                const float bx = bo[col], by = bo[col + 1];
                *(float2*)(out + (size_t)m0 * DOUT + col) =
                    make_float2(acc[mt][n8][0] + bx, acc[mt][n8][1] + by);
                *(float2*)(out + (size_t)m1 * DOUT + col) =
                    make_float2(acc[mt][n8][2] + bx, acc[mt][n8][3] + by);
            }
        }
    }
}

// ===========================================================================
// Flash attention, register-resident mma.sync m16n8k8 tf32 (unchanged R16).
// ===========================================================================
#define KSTR 68
#define VSTR 72
#define AK_OFF   0
#define AV_OFF   (2 * 64 * KSTR)
#define ATTN_SMEM_FLOATS (AV_OFF + 2 * 64 * VSTR)
#define ATTN_SMEM_BYTES  (ATTN_SMEM_FLOATS * 4)   // 71680 B

__global__ void __launch_bounds__(128, 2) attn_tc_kernel()
{
    extern __shared__ float sm[];
    float* sK0 = sm + AK_OFF;
    float* sK1 = sm + AK_OFF + 64 * KSTR;
    float* sV0 = sm + AV_OFF;
    float* sV1 = sm + AV_OFF + 64 * VSTR;

    const int tid  = threadIdx.x;
    const int wid  = tid >> 5;
    const int lane = tid & 31;
    const int gid  = lane >> 2;
    const int tig  = lane & 3;
    const int qt   = blockIdx.x;
    const int bh   = blockIdx.y;
    const int qBase = qt * 128;
    const int wr    = wid * 32;

    const size_t plane = (size_t)BATCH * NH * SEQ * DH;
    const float* Qg = g_qkv + (size_t)bh * SEQ * DH + (size_t)qBase * DH;
    const float* Kg = g_qkv + plane + (size_t)bh * SEQ * DH;
    const float* Vg = g_qkv + 2 * plane + (size_t)bh * SEQ * DH;

    #pragma unroll
    for (int j = 0; j < 16; j++) {
        int i = tid + j * 128;
        int r = i >> 4, c = (i & 15) * 4;
        float* dst = (r < 64) ? (sK0 + r * KSTR + c) : (sK1 + (r - 64) * KSTR + c);
        *(float4*)dst = *(const float4*)(Qg + r * 64 + c);
    }
    __syncthreads();

    uint32_t qa[2][8][4];
    #pragma unroll
    for (int mt = 0; mt < 2; mt++) {
        const int r0 = wr + mt * 16 + gid;
        const float* q0 = (r0 < 64) ? (sK0 + r0 * KSTR) : (sK1 + (r0 - 64) * KSTR);
        const float* q1 = (r0 + 8 < 64) ? (sK0 + (r0 + 8) * KSTR) : (sK1 + (r0 - 56) * KSTR);
        #pragma unroll
        for (int ks = 0; ks < 8; ks++) {
            qa[mt][ks][0] = *(const uint32_t*)(q0 + ks * 8 + tig);
            qa[mt][ks][1] = *(const uint32_t*)(q1 + ks * 8 + tig);
            qa[mt][ks][2] = *(const uint32_t*)(q0 + ks * 8 + tig + 4);
            qa[mt][ks][3] = *(const uint32_t*)(q1 + ks * 8 + tig + 4);
        }
    }
    __syncthreads();

    float oc[2][8][4];
    #pragma unroll
    for (int mt = 0; mt < 2; mt++)
        #pragma unroll
        for (int jo = 0; jo < 8; jo++)
            #pragma unroll
            for (int e = 0; e < 4; e++) oc[mt][jo][e] = 0.0f;
    float m_run[2][2] = {{-1e30f, -1e30f}, {-1e30f, -1e30f}};
    float l_run[2][2] = {{0.f, 0.f}, {0.f, 0.f}};
    const float SCALE2 = 0.125f * 1.44269504088896340736f;

    auto issueKV = [&](int kt, int buf) {
        const float* ksrc = Kg + (size_t)kt * 64 * 64;
        const float* vsrc = Vg + (size_t)kt * 64 * 64;
        float* kd = buf ? sK1 : sK0;
        float* vd = buf ? sV1 : sV0;
        #pragma unroll
        for (int j = 0; j < 8; j++) {
            int i = tid + j * 128;
            int r = i >> 4, c = (i & 15) * 4;
            CP_ASYNC16(smem_u32(kd + r * KSTR + c), ksrc + r * 64 + c);
            CP_ASYNC16(smem_u32(vd + r * VSTR + c), vsrc + r * 64 + c);
        }
        CP_COMMIT();
    };

    const int nkt = qt * 2 + 2;
    issueKV(0, 0);

    for (int kt = 0; kt < nkt; kt++) {
        const int buf = kt & 1;
        __syncthreads();
        if (kt + 1 < nkt) { issueKV(kt + 1, buf ^ 1); CP_WAIT1(); }
        else              { CP_WAIT0(); }
        __syncthreads();

        const float* kb = buf ? sK1 : sK0;
        const float* vb = buf ? sV1 : sV0;

        float sc[2][8][4];
        #pragma unroll
        for (int mt = 0; mt < 2; mt++)
            #pragma unroll
            for (int j = 0; j < 8; j++)
                #pragma unroll
                for (int e = 0; e < 4; e++) sc[mt][j][e] = 0.0f;

        #pragma unroll
        for (int j = 0; j < 8; j++) {
            const float* krow = kb + (j * 8 + gid) * KSTR;
            #pragma unroll
            for (int ks = 0; ks < 8; ks++) {
                uint32_t b0 = *(const uint32_t*)(krow + ks * 8 + tig);
                uint32_t b1 = *(const uint32_t*)(krow + ks * 8 + tig + 4);
                mma8(sc[0][j], qa[0][ks], b0, b1);
                mma8(sc[1][j], qa[1][ks], b0, b1);
            }
        }

        const int kBase = kt * 64;
        const bool needMask = (kt >= 2 * qt);
        float corr[2][2];
        #pragma unroll
        for (int mt = 0; mt < 2; mt++) {
            #pragma unroll
            for (int rh = 0; rh < 2; rh++) {
                const int qi = qBase + wr + mt * 16 + gid + rh * 8;
                float tmax = -1e30f;
                if (needMask) {
                    #pragma unroll
                    for (int j = 0; j < 8; j++) {
                        int key0 = kBase + j * 8 + 2 * tig;
                        float v0 = sc[mt][j][rh * 2 + 0];
                        float v1 = sc[mt][j][rh * 2 + 1];
                        v0 = (key0     <= qi) ? v0 * SCALE2 : -1e30f;
                        v1 = (key0 + 1 <= qi) ? v1 * SCALE2 : -1e30f;
                        sc[mt][j][rh * 2 + 0] = v0;
                        sc[mt][j][rh * 2 + 1] = v1;
                        tmax = fmaxf(tmax, fmaxf(v0, v1));
                    }
                } else {
                    #pragma unroll
                    for (int j = 0; j < 8; j++) {
                        float v0 = sc[mt][j][rh * 2 + 0] * SCALE2;
                        float v1 = sc[mt][j][rh * 2 + 1] * SCALE2;
                        sc[mt][j][rh * 2 + 0] = v0;
                        sc[mt][j][rh * 2 + 1] = v1;
                        tmax = fmaxf(tmax, fmaxf(v0, v1));
                    }
                }
                tmax = fmaxf(tmax, __shfl_xor_sync(0xffffffffu, tmax, 1));
                tmax = fmaxf(tmax, __shfl_xor_sync(0xffffffffu, tmax, 2));
                float m_new = fmaxf(m_run[mt][rh], tmax);
                float cr = exp2f(m_run[mt][rh] - m_new);
                corr[mt][rh] = cr;
                float psum = 0.0f;
                #pragma unroll
                for (int j = 0; j < 8; j++) {
                    float p0 = exp2f(sc[mt][j][rh * 2 + 0] - m_new);
                    float p1 = exp2f(sc[mt][j][rh * 2 + 1] - m_new);
                    sc[mt][j][rh * 2 + 0] = p0;
                    sc[mt][j][rh * 2 + 1] = p1;
                    psum += p0 + p1;
                }
                psum += __shfl_xor_sync(0xffffffffu, psum, 1);
                psum += __shfl_xor_sync(0xffffffffu, psum, 2);
                l_run[mt][rh] = l_run[mt][rh] * cr + psum;
                m_run[mt][rh] = m_new;
            }
        }
        #pragma unroll
        for (int mt = 0; mt < 2; mt++)
            #pragma unroll
            for (int jo = 0; jo < 8; jo++) {
                oc[mt][jo][0] *= corr[mt][0];
                oc[mt][jo][1] *= corr[mt][0];
                oc[mt][jo][2] *= corr[mt][1];
                oc[mt][jo][3] *= corr[mt][1];
            }

        const int src0 = (lane & ~3) | (tig >> 1);
        const int src1 = src0 + 2;
        const bool odd = (tig & 1);
        #pragma unroll
        for (int ks = 0; ks < 8; ks++) {
            uint32_t pa[2][4];
            #pragma unroll
            for (int mt = 0; mt < 2; mt++) {
                float c0 = sc[mt][ks][0], c1 = sc[mt][ks][1];
                float c2 = sc[mt][ks][2], c3 = sc[mt][ks][3];
                float v00 = __shfl_sync(0xffffffffu, c0, src0);
                float v01 = __shfl_sync(0xffffffffu, c1, src0);
                float v10 = __shfl_sync(0xffffffffu, c2, src0);
                float v11 = __shfl_sync(0xffffffffu, c3, src0);
                float v02 = __shfl_sync(0xffffffffu, c0, src1);
                float v03 = __shfl_sync(0xffffffffu, c1, src1);
                float v12 = __shfl_sync(0xffffffffu, c2, src1);
                float v13 = __shfl_sync(0xffffffffu, c3, src1);
                pa[mt][0] = tf32_bits(odd ? v01 : v00);
                pa[mt][1] = tf32_bits(odd ? v11 : v10);
                pa[mt][2] = tf32_bits(odd ? v03 : v02);
                pa[mt][3] = tf32_bits(odd ? v13 : v12);
            }
            const float* vr0 = vb + (ks * 8 + tig) * VSTR;
            const float* vr1 = vb + (ks * 8 + tig + 4) * VSTR;
            #pragma unroll
            for (int jo = 0; jo < 8; jo++) {
                uint32_t b0 = *(const uint32_t*)(vr0 + jo * 8 + gid);
                uint32_t b1 = *(const uint32_t*)(vr1 + jo * 8 + gid);
                mma8(oc[0][jo], pa[0], b0, b1);
                mma8(oc[1][jo], pa[1], b0, b1);
            }
        }
    }

    const int b = bh >> 4;
    const int h = bh & (NH - 1);
    #pragma unroll
    for (int mt = 0; mt < 2; mt++) {
        const float inv0 = 1.0f / l_run[mt][0];
        const float inv1 = 1.0f / l_run[mt][1];
        const int r0 = qBase + wr + mt * 16 + gid;
        float* d0 = g_ctx + ((size_t)(b * SEQ + r0)) * DOUT + h * DH;
        float* d1 = g_ctx + ((size_t)(b * SEQ + r0 + 8)) * DOUT + h * DH;
        #pragma unroll
        for (int jo = 0; jo < 8; jo++) {
            const int c0 = jo * 8 + 2 * tig;
            float2 w0 = make_float2(cvt_tf32_rn(oc[mt][jo][0] * inv0),
                                    cvt_tf32_rn(oc[mt][jo][1] * inv0));
            float2 w1 = make_float2(cvt_tf32_rn(oc[mt][jo][2] * inv1),
                                    cvt_tf32_rn(oc[mt][jo][3] * inv1));
            *(float2*)(d0 + c0) = w0;
            *(float2*)(d1 + c0) = w1;
        }
    }
}

// ---------------------------------------------------------------------------
// Launch
// ---------------------------------------------------------------------------
extern "C" void kernel_launch(void* const* d_in, const int* in_sizes, int n_in,
                              void* d_out, int out_size)
{
    const float* x  = (const float*)d_in[0];
    const float* Wq = (const float*)d_in[1];
    const float* Wk = (const float*)d_in[2];
    const float* Wv = (const float*)d_in[3];
    const float* Wo = (const float*)d_in[4];
    const float* bo = (const float*)d_in[5];
    float* out = (float*)d_out;

    cudaFuncSetAttribute(gemm_tc_kernel<0>, cudaFuncAttributeMaxDynamicSharedMemorySize, SMEM_BYTES);
    cudaFuncSetAttribute(gemm_tc_kernel<1>, cudaFuncAttributeMaxDynamicSharedMemorySize, SMEM_BYTES);
    cudaFuncSetAttribute(attn_tc_kernel,    cudaFuncAttributeMaxDynamicSharedMemorySize, ATTN_SMEM_BYTES);

    dim3 gt(DOUT / 32, DIN / 32, 4);
    transpose_w_kernel<<<gt, 256>>>(Wq, Wk, Wv, Wo);

    dim3 g1(MTOT / 128, DOUT / 128, 3);
    gemm_tc_kernel<0><<<g1, 128, SMEM_BYTES>>>(x, nullptr, nullptr);

    dim3 g2(SEQ / 128, BATCH * NH);
    attn_tc_kernel<<<g2, 128, ATTN_SMEM_BYTES>>>();

    dim3 g3(MTOT / 128, DOUT / 128, 1);
    gemm_tc_kernel<1><<<g3, 128, SMEM_BYTES>>>(nullptr, bo, out);   // A = g_ctx in-kernel

    bias_add:;  // label unused; bias fused into gemm<1> epilogue
}